// round 13
// baseline (speedup 1.0000x reference)
#include <cuda_runtime.h>
#include <cuda_bf16.h>
#include <cuda_fp16.h>
#include <cstdint>
#include <math.h>

#define SEQLEN 2048
#define DIM    4096
#define NH     32
#define HD     128
#define NKV    8
#define QKV_N  6144
#define KV_ROW 1024
#define WIN    4096
#define SCALE  0.08838834764831845f

// ---------------- scratch (device globals) ----------------------------------
__device__ __half g_xh [(size_t)SEQLEN * DIM];
__device__ __half g_xl [(size_t)SEQLEN * DIM];
__device__ __half g_ah [(size_t)SEQLEN * DIM];
__device__ __half g_al [(size_t)SEQLEN * DIM];
__device__ __half g_wq [(size_t)QKV_N * DIM];
__device__ __half g_wo [(size_t)DIM * DIM];
__device__ __nv_bfloat16 g_qhi[(size_t)NH  * SEQLEN * HD];
__device__ __nv_bfloat16 g_qlo[(size_t)NH  * SEQLEN * HD];
__device__ __nv_bfloat16 g_khi[(size_t)NKV * SEQLEN * HD];
__device__ __nv_bfloat16 g_klo[(size_t)NKV * SEQLEN * HD];
__device__ __nv_bfloat16 g_vhi[(size_t)NKV * SEQLEN * HD];
__device__ __nv_bfloat16 g_vlo[(size_t)NKV * SEQLEN * HD];

// ---------------- common PTX helpers ----------------------------------------
__device__ __forceinline__ void cp16(uint32_t d, const void* g) {
    asm volatile("cp.async.cg.shared.global [%0], [%1], 16;\n"
                 :: "r"(d), "l"(__cvta_generic_to_global(g)) : "memory");
}
__device__ __forceinline__ void ldm4(uint32_t& r0, uint32_t& r1,
                                     uint32_t& r2, uint32_t& r3, uint32_t a) {
    asm volatile("ldmatrix.sync.aligned.m8n8.x4.shared.b16 {%0,%1,%2,%3}, [%4];"
                 : "=r"(r0), "=r"(r1), "=r"(r2), "=r"(r3) : "r"(a));
}
__device__ __forceinline__ void ldm4t(uint32_t& r0, uint32_t& r1,
                                      uint32_t& r2, uint32_t& r3, uint32_t a) {
    asm volatile("ldmatrix.sync.aligned.m8n8.x4.trans.shared.b16 {%0,%1,%2,%3}, [%4];"
                 : "=r"(r0), "=r"(r1), "=r"(r2), "=r"(r3) : "r"(a));
}
__device__ __forceinline__ void mma_bf16(float* c, const uint32_t* a,
                                         const uint32_t* b) {
    asm volatile(
        "mma.sync.aligned.m16n8k16.row.col.f32.bf16.bf16.f32 "
        "{%0,%1,%2,%3}, {%4,%5,%6,%7}, {%8,%9}, {%0,%1,%2,%3};"
        : "+f"(c[0]), "+f"(c[1]), "+f"(c[2]), "+f"(c[3])
        : "r"(a[0]), "r"(a[1]), "r"(a[2]), "r"(a[3]), "r"(b[0]), "r"(b[1]));
}
__device__ __forceinline__ void mma_f16(float* c, const uint32_t* a,
                                        const uint32_t* b) {
    asm volatile(
        "mma.sync.aligned.m16n8k16.row.col.f32.f16.f16.f32 "
        "{%0,%1,%2,%3}, {%4,%5,%6,%7}, {%8,%9}, {%0,%1,%2,%3};"
        : "+f"(c[0]), "+f"(c[1]), "+f"(c[2]), "+f"(c[3])
        : "r"(a[0]), "r"(a[1]), "r"(a[2]), "r"(a[3]), "r"(b[0]), "r"(b[1]));
}
__device__ __forceinline__ void split2(float x, float y, uint32_t& hi, uint32_t& lo) {
    __nv_bfloat162 h = __floats2bfloat162_rn(x, y);
    float rx = x - __bfloat162float(h.x);
    float ry = y - __bfloat162float(h.y);
    __nv_bfloat162 r = __floats2bfloat162_rn(rx, ry);
    hi = *(uint32_t*)&h; lo = *(uint32_t*)&r;
}
__device__ __forceinline__ void split2bf(float x, float y,
                                         __nv_bfloat162& h2, __nv_bfloat162& l2) {
    h2 = __floats2bfloat162_rn(x, y);
    float rx = x - __bfloat162float(h2.x);
    float ry = y - __bfloat162float(h2.y);
    l2 = __floats2bfloat162_rn(rx, ry);
}

// ---------------- combined pre-GEMM conversion (x hi/lo + Wqkv fp16) --------
#define XQ4  ((long long)SEQLEN * DIM / 4)      // 2,097,152
#define WQQ4 ((long long)QKV_N * DIM / 4)       // 6,291,456
__global__ __launch_bounds__(256) void convert_pre(
    const float* __restrict__ x, __half* __restrict__ xh, __half* __restrict__ xl,
    const float* __restrict__ wq, __half* __restrict__ wqh)
{
    long long i = (long long)blockIdx.x * 256 + threadIdx.x;
    if (i < XQ4) {
        float4 v = ((const float4*)x)[i];
        float vv[4] = {v.x, v.y, v.z, v.w};
        union { unsigned long long u; __half h[4]; } H, L;
#pragma unroll
        for (int j = 0; j < 4; j++) {
            __half h = __float2half_rn(vv[j]);
            H.h[j] = h;
            L.h[j] = __float2half_rn(vv[j] - __half2float(h));
        }
        ((unsigned long long*)xh)[i] = H.u;
        ((unsigned long long*)xl)[i] = L.u;
    } else if (i < XQ4 + WQQ4) {
        long long k = i - XQ4;
        float4 v = ((const float4*)wq)[k];
        float vv[4] = {v.x, v.y, v.z, v.w};
        union { unsigned long long u; __half h[4]; } H;
#pragma unroll
        for (int j = 0; j < 4; j++) H.h[j] = __float2half_rn(vv[j]);
        ((unsigned long long*)wqh)[k] = H.u;
    }
}

// ---------------- fp16 2-term mma.sync GEMM: C = A * B^T ---------------------
// CTA 128x128, 4 warps (2x2), warp tile 64x64. K = 4096, KC = 64.
// mode 0: plain fp32 store. mode 1: fused RoPE/scale/split QKV epilogue,
//         plus worker CTAs (bx >= 48) that convert Wo and copy cache tails.
#define GK       4096
#define NCHUNK   (GK / 64)               // 64
#define PTILEB   (128 * 128)             // 16384 per part-tile
#define STAGEB   (3 * PTILEB)            // 49152
#define GEMM_SMEM (2 * STAGEB)           // 98304
#define NBX      (QKV_N / 128)           // 48 real column blocks in mode 1
#define EXTRA_X  13                      // worker CTAs per by row (13*16 = 208)
#define WOQ4     ((long long)DIM * DIM / 4)                 // 4,194,304
#define CKQ4     ((long long)(WIN - SEQLEN) * KV_ROW / 4)   // 524,288

__global__ __launch_bounds__(128, 2) void gemm_mma(
    const __half* __restrict__ Ah, const __half* __restrict__ Al,
    const __half* __restrict__ Bh, float* __restrict__ C, int N, int mode,
    const float* __restrict__ cosf_, const float* __restrict__ sinf_,
    float* __restrict__ kcache, float* __restrict__ vcache,
    __nv_bfloat16* __restrict__ qhi, __nv_bfloat16* __restrict__ qlo,
    __nv_bfloat16* __restrict__ khi, __nv_bfloat16* __restrict__ klo,
    __nv_bfloat16* __restrict__ vhi, __nv_bfloat16* __restrict__ vlo,
    const float* __restrict__ wo_src, __half* __restrict__ wo_dst,
    const float* __restrict__ in_ck, const float* __restrict__ in_cv)
{
    const int tid = threadIdx.x;

    // ---- worker CTAs: Wo convert + cache tail copies (mode 1 only) ---------
    if (mode == 1 && blockIdx.x >= NBX) {
        const long long wcta = (long long)(blockIdx.x - NBX) + EXTRA_X * blockIdx.y;
        const long long stride = (long long)EXTRA_X * 16 * 128;
        const long long coff = (long long)SEQLEN * KV_ROW / 4;
        for (long long i = wcta * 128 + tid; i < WOQ4 + 2 * CKQ4; i += stride) {
            if (i < WOQ4) {
                float4 v = ((const float4*)wo_src)[i];
                float vv[4] = {v.x, v.y, v.z, v.w};
                union { unsigned long long u; __half h[4]; } H;
#pragma unroll
                for (int j = 0; j < 4; j++) H.h[j] = __float2half_rn(vv[j]);
                ((unsigned long long*)wo_dst)[i] = H.u;
            } else if (i < WOQ4 + CKQ4) {
                long long j = i - WOQ4 + coff;
                ((float4*)kcache)[j] = ((const float4*)in_ck)[j];
            } else {
                long long j = i - WOQ4 - CKQ4 + coff;
                ((float4*)vcache)[j] = ((const float4*)in_cv)[j];
            }
        }
        return;
    }

    extern __shared__ __align__(128) char smraw[];
    const uint32_t sb = (uint32_t)__cvta_generic_to_shared(smraw);

    const int w   = tid >> 5;
    const int l   = tid & 31;
    const int wm  = w & 1;          // 0-1 : 64-row slab
    const int wn  = w >> 1;         // 0-1 : 64-col slab

    const size_t arow_g = (size_t)blockIdx.y * 128 * GK;
    const size_t brow_g = (size_t)blockIdx.x * 128 * GK;
    const char* gp[3] = { (const char*)(Ah + arow_g), (const char*)(Al + arow_g),
                          (const char*)(Bh + brow_g) };

    auto load_chunk = [&](int t, uint32_t st) {
        const size_t gk = (size_t)t * 128;
#pragma unroll
        for (int part = 0; part < 3; part++) {
#pragma unroll
            for (int j = 0; j < 8; j++) {
                int slot = tid + j * 128;
                int r = slot >> 3, c = slot & 7;
                uint32_t dc = (uint32_t)((c ^ (r & 7)) * 16);
                cp16(st + part * PTILEB + r * 128 + dc,
                     gp[part] + (size_t)r * (GK * 2) + gk + c * 16);
            }
        }
    };

    const int arow = wm * 64 + (l & 15);
    const uint32_t arb  = (uint32_t)(arow * 128);
    const int axor = arow & 7;
    const int ac0 = (l >> 4);
    const int l2 = l & 7, sel = l >> 3;
    const int brow = wn * 64 + (sel >> 1) * 8 + l2;
    const uint32_t brb  = (uint32_t)(brow * 128);
    const int bxor = brow & 7;
    const int bc0 = (sel & 1);

    float acc[4][8][4];
#pragma unroll
    for (int mt = 0; mt < 4; mt++)
#pragma unroll
        for (int nt = 0; nt < 8; nt++)
#pragma unroll
            for (int i = 0; i < 4; i++) acc[mt][nt][i] = 0.f;

    load_chunk(0, sb);
    asm volatile("cp.async.commit_group;" ::: "memory");

    for (int k = 0; k < NCHUNK; k++) {
        asm volatile("cp.async.wait_group 0;" ::: "memory");
        __syncthreads();
        if (k + 1 < NCHUNK) {
            load_chunk(k + 1, sb + ((k + 1) & 1) * STAGEB);
            asm volatile("cp.async.commit_group;" ::: "memory");
        }

        const uint32_t st = sb + (k & 1) * STAGEB;
#pragma unroll
        for (int ks = 0; ks < 4; ks++) {
            const uint32_t ach = (uint32_t)(((ks * 2 + ac0) ^ axor) * 16);
            const uint32_t bch = (uint32_t)(((ks * 2 + bc0) ^ bxor) * 16);

            uint32_t ah[4][4], bh[8][2];
#pragma unroll
            for (int mt = 0; mt < 4; mt++)
                ldm4(ah[mt][0], ah[mt][1], ah[mt][2], ah[mt][3],
                     st + arb + mt * 2048 + ach);
#pragma unroll
            for (int np = 0; np < 4; np++)
                ldm4(bh[2*np][0], bh[2*np][1], bh[2*np+1][0], bh[2*np+1][1],
                     st + 2 * PTILEB + brb + np * 2048 + bch);
#pragma unroll
            for (int mt = 0; mt < 4; mt++)
#pragma unroll
                for (int nt = 0; nt < 8; nt++)
                    mma_f16(acc[mt][nt], ah[mt], bh[nt]);

            uint32_t al[4][4];
#pragma unroll
            for (int mt = 0; mt < 4; mt++)
                ldm4(al[mt][0], al[mt][1], al[mt][2], al[mt][3],
                     st + PTILEB + arb + mt * 2048 + ach);
#pragma unroll
            for (int mt = 0; mt < 4; mt++)
#pragma unroll
                for (int nt = 0; nt < 8; nt++)
                    mma_f16(acc[mt][nt], al[mt], bh[nt]);
        }
    }

    const int crow = blockIdx.y * 128 + wm * 64 + (l >> 2);
    const int ccolbase = wn * 64 + (l & 3) * 2;

    if (mode == 0) {
        const int ccol = blockIdx.x * 128 + ccolbase;
#pragma unroll
        for (int mt = 0; mt < 4; mt++) {
#pragma unroll
            for (int nt = 0; nt < 8; nt++) {
                float* p0 = C + (size_t)(crow + mt * 16)     * N + ccol + nt * 8;
                float* p1 = C + (size_t)(crow + mt * 16 + 8) * N + ccol + nt * 8;
                *(float2*)p0 = make_float2(acc[mt][nt][0], acc[mt][nt][1]);
                *(float2*)p1 = make_float2(acc[mt][nt][2], acc[mt][nt][3]);
            }
        }
        return;
    }

    // ---- mode 1: fused QKV epilogue (one head per CTA column block) --------
    const int bx = blockIdx.x;
#pragma unroll
    for (int mt = 0; mt < 4; mt++) {
#pragma unroll
        for (int j = 0; j < 2; j++) {
            const int s = crow + mt * 16 + j * 8;
#pragma unroll
            for (int nt = 0; nt < 8; nt++) {
                float v0 = acc[mt][nt][j * 2 + 0];
                float v1 = acc[mt][nt][j * 2 + 1];
                const int d = ccolbase + nt * 8;
                if (bx < NH) {                      // Q head bx: rope + scale
                    const int f = d >> 1;
                    float c  = __ldg(cosf_ + s * 64 + f);
                    float sn = __ldg(sinf_ + s * 64 + f);
                    float o1 = (v0 * c - v1 * sn) * SCALE;
                    float o2 = (v0 * sn + v1 * c) * SCALE;
                    size_t o = ((size_t)bx * SEQLEN + s) * HD + d;
                    __nv_bfloat162 h2, l2v;
                    split2bf(o1, o2, h2, l2v);
                    *(__nv_bfloat162*)(qhi + o) = h2;
                    *(__nv_bfloat162*)(qlo + o) = l2v;
                } else if (bx < NH + NKV) {          // K head: rope + cache
                    const int kvh = bx - NH;
                    const int f = d >> 1;
                    float c  = __ldg(cosf_ + s * 64 + f);
                    float sn = __ldg(sinf_ + s * 64 + f);
                    float o1 = v0 * c - v1 * sn;
                    float o2 = v0 * sn + v1 * c;
                    *(float2*)(kcache + (size_t)s * KV_ROW + kvh * HD + d) =
                        make_float2(o1, o2);
                    size_t o = ((size_t)kvh * SEQLEN + s) * HD + d;
                    __nv_bfloat162 h2, l2v;
                    split2bf(o1, o2, h2, l2v);
                    *(__nv_bfloat162*)(khi + o) = h2;
                    *(__nv_bfloat162*)(klo + o) = l2v;
                } else {                             // V head: copy + cache
                    const int kvh = bx - NH - NKV;
                    *(float2*)(vcache + (size_t)s * KV_ROW + kvh * HD + d) =
                        make_float2(v0, v1);
                    size_t o = ((size_t)kvh * SEQLEN + s) * HD + d;
                    __nv_bfloat162 h2, l2v;
                    split2bf(v0, v1, h2, l2v);
                    *(__nv_bfloat162*)(vhi + o) = h2;
                    *(__nv_bfloat162*)(vlo + o) = l2v;
                }
            }
        }
    }
}

// ---------------- tensor-core causal flash attention (double-buffered) ------
#define ASTRIDE 272
#define ATILE   (64 * ASTRIDE)
#define ABUF    (4 * ATILE)
#define ATTN_SMEM (2 * ABUF)

__global__ __launch_bounds__(256, 1) void attn_tc(
    const __nv_bfloat16* __restrict__ Qh, const __nv_bfloat16* __restrict__ Ql,
    const __nv_bfloat16* __restrict__ Kh, const __nv_bfloat16* __restrict__ Kl,
    const __nv_bfloat16* __restrict__ Vh, const __nv_bfloat16* __restrict__ Vl,
    __half* __restrict__ OH, __half* __restrict__ OL)
{
    extern __shared__ __align__(128) char smraw[];
    const uint32_t sb = (uint32_t)__cvta_generic_to_shared(smraw);
    const int tid = threadIdx.x, w = tid >> 5, l = tid & 31;
    const int qt  = (int)gridDim.x - 1 - (int)blockIdx.x;
    const int h   = blockIdx.y;
    const int kvh = h >> 2;

    uint32_t qh_[8][4], ql_[8][4];
    {
        const uint32_t aoff = sb + (uint32_t)((w * 16 + (l & 15)) * ASTRIDE
                                              + (l >> 4) * 16);
        for (int part = 0; part < 2; part++) {
            const __nv_bfloat16* src = part ? Ql : Qh;
            const char* g0 = (const char*)(src + ((size_t)h * SEQLEN + qt * 128) * HD);
            for (int i = tid; i < 2048; i += 256)
                cp16(sb + (uint32_t)((i >> 4) * ASTRIDE + (i & 15) * 16),
                     g0 + (size_t)i * 16);
            asm volatile("cp.async.commit_group;" ::: "memory");
            asm volatile("cp.async.wait_group 0;" ::: "memory");
            __syncthreads();
            uint32_t (*dst)[4] = part ? ql_ : qh_;
#pragma unroll
            for (int g = 0; g < 8; g++)
                ldm4(dst[g][0], dst[g][1], dst[g][2], dst[g][3], aoff + g * 32);
            __syncthreads();
        }
    }

    float o[16][4];
#pragma unroll
    for (int t = 0; t < 16; t++)
#pragma unroll
        for (int i = 0; i < 4; i++) o[t][i] = 0.f;
    float m0 = -1e30f, m1 = -1e30f, l0 = 0.f, l1 = 0.f;

    const int row0 = qt * 128 + w * 16 + (l >> 2);
    const int l2 = l & 7, sel = l >> 3;
    const int nkb = 2 * qt + 2;

    auto load_kv = [&](int kb, uint32_t bufbase) {
        const size_t gbase = (((size_t)kvh * SEQLEN + (size_t)kb * 64) * HD) * 2;
        for (int i = tid; i < 1024; i += 256) {
            uint32_t soff = (uint32_t)((i >> 4) * ASTRIDE + (i & 15) * 16);
            size_t goff = gbase + (size_t)i * 16;
            cp16(bufbase + 0 * ATILE + soff, (const char*)Kh + goff);
            cp16(bufbase + 1 * ATILE + soff, (const char*)Kl + goff);
            cp16(bufbase + 2 * ATILE + soff, (const char*)Vh + goff);
            cp16(bufbase + 3 * ATILE + soff, (const char*)Vl + goff);
        }
        asm volatile("cp.async.commit_group;" ::: "memory");
    };

    int buf = 0;
    load_kv(0, sb);

    for (int kb = 0; kb < nkb; kb++) {
        if (kb + 1 < nkb) {
            load_kv(kb + 1, sb + (buf ^ 1) * ABUF);
            asm volatile("cp.async.wait_group 1;" ::: "memory");
        } else {
            asm volatile("cp.async.wait_group 0;" ::: "memory");
        }
        __syncthreads();
        const uint32_t bbase = sb + buf * ABUF;

        float sc[8][4];
#pragma unroll
        for (int t = 0; t < 8; t++)
#pragma unroll
            for (int i = 0; i < 4; i++) sc[t][i] = 0.f;

#pragma unroll
        for (int g = 0; g < 8; g++) {
#pragma unroll
            for (int n16 = 0; n16 < 4; n16++) {
                uint32_t kaddr = bbase + (uint32_t)((n16 * 16 + (sel >> 1) * 8 + l2)
                                                    * ASTRIDE + (sel & 1) * 16 + g * 32);
                uint32_t bh[2][2], bl[2][2];
                ldm4(bh[0][0], bh[0][1], bh[1][0], bh[1][1], kaddr);
                ldm4(bl[0][0], bl[0][1], bl[1][0], bl[1][1], kaddr + ATILE);
#pragma unroll
                for (int j = 0; j < 2; j++) {
                    int t = n16 * 2 + j;
                    mma_bf16(sc[t], qh_[g], bh[j]);
                    mma_bf16(sc[t], ql_[g], bh[j]);
                    mma_bf16(sc[t], qh_[g], bl[j]);
                }
            }
        }

        if (kb >= 2 * qt) {
#pragma unroll
            for (int t = 0; t < 8; t++) {
                int col = kb * 64 + t * 8 + 2 * (l & 3);
                if (col     > row0)     sc[t][0] = -1e30f;
                if (col + 1 > row0)     sc[t][1] = -1e30f;
                if (col     > row0 + 8) sc[t][2] = -1e30f;
                if (col + 1 > row0 + 8) sc[t][3] = -1e30f;
            }
        }

        float r0m = -1e30f, r1m = -1e30f;
#pragma unroll
        for (int t = 0; t < 8; t++) {
            r0m = fmaxf(r0m, fmaxf(sc[t][0], sc[t][1]));
            r1m = fmaxf(r1m, fmaxf(sc[t][2], sc[t][3]));
        }
        r0m = fmaxf(r0m, __shfl_xor_sync(0xffffffffu, r0m, 1));
        r0m = fmaxf(r0m, __shfl_xor_sync(0xffffffffu, r0m, 2));
        r1m = fmaxf(r1m, __shfl_xor_sync(0xffffffffu, r1m, 1));
        r1m = fmaxf(r1m, __shfl_xor_sync(0xffffffffu, r1m, 2));
        float nm0 = fmaxf(m0, r0m), nm1 = fmaxf(m1, r1m);
        float a0 = __expf(m0 - nm0), a1 = __expf(m1 - nm1);

        float s0 = 0.f, s1 = 0.f;
#pragma unroll
        for (int t = 0; t < 8; t++) {
            sc[t][0] = __expf(sc[t][0] - nm0); s0 += sc[t][0];
            sc[t][1] = __expf(sc[t][1] - nm0); s0 += sc[t][1];
            sc[t][2] = __expf(sc[t][2] - nm1); s1 += sc[t][2];
            sc[t][3] = __expf(sc[t][3] - nm1); s1 += sc[t][3];
        }
        s0 += __shfl_xor_sync(0xffffffffu, s0, 1);
        s0 += __shfl_xor_sync(0xffffffffu, s0, 2);
        s1 += __shfl_xor_sync(0xffffffffu, s1, 1);
        s1 += __shfl_xor_sync(0xffffffffu, s1, 2);
        l0 = l0 * a0 + s0;
        l1 = l1 * a1 + s1;
        m0 = nm0; m1 = nm1;
#pragma unroll
        for (int t = 0; t < 16; t++) {
            o[t][0] *= a0; o[t][1] *= a0;
            o[t][2] *= a1; o[t][3] *= a1;
        }

#pragma unroll
        for (int g = 0; g < 4; g++) {
            uint32_t aph[4], apl[4];
            split2(sc[2*g][0],   sc[2*g][1],   aph[0], apl[0]);
            split2(sc[2*g][2],   sc[2*g][3],   aph[1], apl[1]);
            split2(sc[2*g+1][0], sc[2*g+1][1], aph[2], apl[2]);
            split2(sc[2*g+1][2], sc[2*g+1][3], aph[3], apl[3]);
#pragma unroll
            for (int n16 = 0; n16 < 8; n16++) {
                uint32_t vaddr = bbase + 2 * ATILE
                    + (uint32_t)((g * 16 + (l & 15)) * ASTRIDE
                                 + n16 * 32 + (l >> 4) * 16);
                uint32_t bvh[2][2], bvl[2][2];
                ldm4t(bvh[0][0], bvh[0][1], bvh[1][0], bvh[1][1], vaddr);
                ldm4t(bvl[0][0], bvl[0][1], bvl[1][0], bvl[1][1], vaddr + ATILE);
#pragma unroll
                for (int j = 0; j < 2; j++) {
                    int t = n16 * 2 + j;
                    mma_bf16(o[t], aph, bvh[j]);
                    mma_bf16(o[t], apl, bvh[j]);
                    mma_bf16(o[t], aph, bvl[j]);
                }
            }
        }
        __syncthreads();
        buf ^= 1;
    }

    float i0 = 1.f / l0, i1 = 1.f / l1;
    const int colb = h * HD + 2 * (l & 3);
#pragma unroll
    for (int t = 0; t < 16; t++) {
        {
            float v0 = o[t][0] * i0, v1 = o[t][1] * i0;
            __half h0 = __float2half_rn(v0), h1 = __float2half_rn(v1);
            __half e0 = __float2half_rn(v0 - __half2float(h0));
            __half e1 = __float2half_rn(v1 - __half2float(h1));
            size_t off = (size_t)row0 * DIM + colb + t * 8;
            *(__half2*)(OH + off) = __halves2half2(h0, h1);
            *(__half2*)(OL + off) = __halves2half2(e0, e1);
        }
        {
            float v0 = o[t][2] * i1, v1 = o[t][3] * i1;
            __half h0 = __float2half_rn(v0), h1 = __float2half_rn(v1);
            __half e0 = __float2half_rn(v0 - __half2float(h0));
            __half e1 = __float2half_rn(v1 - __half2float(h1));
            size_t off = (size_t)(row0 + 8) * DIM + colb + t * 8;
            *(__half2*)(OH + off) = __halves2half2(h0, h1);
            *(__half2*)(OL + off) = __halves2half2(e0, e1);
        }
    }
}

// ---------------- launch ----------------------------------------------------
extern "C" void kernel_launch(void* const* d_in, const int* in_sizes, int n_in,
                              void* d_out, int out_size)
{
    const float* x     = (const float*)d_in[0];
    const float* cosf_ = (const float*)d_in[1];
    const float* sinf_ = (const float*)d_in[2];
    const float* in_ck = (const float*)d_in[5];
    const float* in_cv = (const float*)d_in[6];
    const float* Wqkv  = (const float*)d_in[7];
    const float* Wo    = (const float*)d_in[8];

    float* out     = (float*)d_out;
    float* cache_k = out + (size_t)SEQLEN * DIM;
    float* cache_v = cache_k + (size_t)WIN * KV_ROW;

    __half *xh_p, *xl_p, *ah_p, *al_p, *wq_p, *wo_p;
    __nv_bfloat16 *qhi_p, *qlo_p, *khi_p, *klo_p, *vhi_p, *vlo_p;
    cudaGetSymbolAddress((void**)&xh_p,   g_xh);
    cudaGetSymbolAddress((void**)&xl_p,   g_xl);
    cudaGetSymbolAddress((void**)&ah_p,   g_ah);
    cudaGetSymbolAddress((void**)&al_p,   g_al);
    cudaGetSymbolAddress((void**)&wq_p,   g_wq);
    cudaGetSymbolAddress((void**)&wo_p,   g_wo);
    cudaGetSymbolAddress((void**)&qhi_p,  g_qhi);
    cudaGetSymbolAddress((void**)&qlo_p,  g_qlo);
    cudaGetSymbolAddress((void**)&khi_p,  g_khi);
    cudaGetSymbolAddress((void**)&klo_p,  g_klo);
    cudaGetSymbolAddress((void**)&vhi_p,  g_vhi);
    cudaGetSymbolAddress((void**)&vlo_p,  g_vlo);

    cudaFuncSetAttribute(gemm_mma, cudaFuncAttributeMaxDynamicSharedMemorySize,
                         GEMM_SMEM);
    cudaFuncSetAttribute(attn_tc, cudaFuncAttributeMaxDynamicSharedMemorySize,
                         ATTN_SMEM);

    // 0) combined pre-GEMM conversions (x hi/lo + Wqkv)
    {
        long long total = XQ4 + WQQ4;
        convert_pre<<<(unsigned)((total + 255) / 256), 256>>>(x, xh_p, xl_p,
                                                              Wqkv, wq_p);
    }

    // 1) QKV projection w/ fused RoPE/scale/cache/split epilogue (mode 1)
    //    + worker CTAs (bx >= 48): Wo fp32->fp16 convert, cache tail copies
    gemm_mma<<<dim3(NBX + EXTRA_X, SEQLEN / 128), 128, GEMM_SMEM>>>(
        xh_p, xl_p, wq_p, nullptr, QKV_N, 1,
        cosf_, sinf_, cache_k, cache_v,
        qhi_p, qlo_p, khi_p, klo_p, vhi_p, vlo_p,
        Wo, wo_p, in_ck, in_cv);

    // 2) tensor-core causal flash attention, fp16 hi/lo epilogue
    attn_tc<<<dim3(SEQLEN / 128, NH), 256, ATTN_SMEM>>>(
        qhi_p, qlo_p, khi_p, klo_p, vhi_p, vlo_p, ah_p, al_p);

    // 3) output projection (mode 0, plain fp32 store)
    gemm_mma<<<dim3(DIM / 128, SEQLEN / 128), 128, GEMM_SMEM>>>(
        ah_p, al_p, wo_p, out, DIM, 0,
        nullptr, nullptr, nullptr, nullptr,
        nullptr, nullptr, nullptr, nullptr, nullptr, nullptr,
        nullptr, nullptr, nullptr, nullptr);
}

// round 14
// speedup vs baseline: 1.0264x; 1.0264x over previous
#include <cuda_runtime.h>
#include <cuda_bf16.h>
#include <cuda_fp16.h>
#include <cstdint>
#include <math.h>

#define SEQLEN 2048
#define DIM    4096
#define NH     32
#define HD     128
#define NKV    8
#define QKV_N  6144
#define KV_ROW 1024
#define WIN    4096
#define SCALE  0.08838834764831845f

// ---------------- scratch (device globals) ----------------------------------
__device__ __half g_xh [(size_t)SEQLEN * DIM];
__device__ __half g_xl [(size_t)SEQLEN * DIM];
__device__ __half g_ah [(size_t)SEQLEN * DIM];
__device__ __half g_al [(size_t)SEQLEN * DIM];
__device__ __half g_wq [(size_t)QKV_N * DIM];
__device__ __half g_wo [(size_t)DIM * DIM];
__device__ __nv_bfloat16 g_qhi[(size_t)NH  * SEQLEN * HD];
__device__ __nv_bfloat16 g_qlo[(size_t)NH  * SEQLEN * HD];
__device__ __nv_bfloat16 g_khi[(size_t)NKV * SEQLEN * HD];
__device__ __nv_bfloat16 g_klo[(size_t)NKV * SEQLEN * HD];
__device__ __nv_bfloat16 g_vhi[(size_t)NKV * SEQLEN * HD];
__device__ __nv_bfloat16 g_vlo[(size_t)NKV * SEQLEN * HD];

// ---------------- common PTX helpers ----------------------------------------
__device__ __forceinline__ void cp16(uint32_t d, const void* g) {
    asm volatile("cp.async.cg.shared.global [%0], [%1], 16;\n"
                 :: "r"(d), "l"(__cvta_generic_to_global(g)) : "memory");
}
__device__ __forceinline__ void ldm4(uint32_t& r0, uint32_t& r1,
                                     uint32_t& r2, uint32_t& r3, uint32_t a) {
    asm volatile("ldmatrix.sync.aligned.m8n8.x4.shared.b16 {%0,%1,%2,%3}, [%4];"
                 : "=r"(r0), "=r"(r1), "=r"(r2), "=r"(r3) : "r"(a));
}
__device__ __forceinline__ void ldm4t(uint32_t& r0, uint32_t& r1,
                                      uint32_t& r2, uint32_t& r3, uint32_t a) {
    asm volatile("ldmatrix.sync.aligned.m8n8.x4.trans.shared.b16 {%0,%1,%2,%3}, [%4];"
                 : "=r"(r0), "=r"(r1), "=r"(r2), "=r"(r3) : "r"(a));
}
__device__ __forceinline__ void mma_bf16(float* c, const uint32_t* a,
                                         const uint32_t* b) {
    asm volatile(
        "mma.sync.aligned.m16n8k16.row.col.f32.bf16.bf16.f32 "
        "{%0,%1,%2,%3}, {%4,%5,%6,%7}, {%8,%9}, {%0,%1,%2,%3};"
        : "+f"(c[0]), "+f"(c[1]), "+f"(c[2]), "+f"(c[3])
        : "r"(a[0]), "r"(a[1]), "r"(a[2]), "r"(a[3]), "r"(b[0]), "r"(b[1]));
}
__device__ __forceinline__ void mma_f16(float* c, const uint32_t* a,
                                        const uint32_t* b) {
    asm volatile(
        "mma.sync.aligned.m16n8k16.row.col.f32.f16.f16.f32 "
        "{%0,%1,%2,%3}, {%4,%5,%6,%7}, {%8,%9}, {%0,%1,%2,%3};"
        : "+f"(c[0]), "+f"(c[1]), "+f"(c[2]), "+f"(c[3])
        : "r"(a[0]), "r"(a[1]), "r"(a[2]), "r"(a[3]), "r"(b[0]), "r"(b[1]));
}
__device__ __forceinline__ void split2(float x, float y, uint32_t& hi, uint32_t& lo) {
    __nv_bfloat162 h = __floats2bfloat162_rn(x, y);
    float rx = x - __bfloat162float(h.x);
    float ry = y - __bfloat162float(h.y);
    __nv_bfloat162 r = __floats2bfloat162_rn(rx, ry);
    hi = *(uint32_t*)&h; lo = *(uint32_t*)&r;
}
__device__ __forceinline__ void split2bf(float x, float y,
                                         __nv_bfloat162& h2, __nv_bfloat162& l2) {
    h2 = __floats2bfloat162_rn(x, y);
    float rx = x - __bfloat162float(h2.x);
    float ry = y - __bfloat162float(h2.y);
    l2 = __floats2bfloat162_rn(rx, ry);
}

// ---------------- single prep kernel: all converts + cache tail copies ------
#define XQ4  ((long long)SEQLEN * DIM / 4)                  // 2,097,152
#define WQQ4 ((long long)QKV_N * DIM / 4)                   // 6,291,456
#define WOQ4 ((long long)DIM * DIM / 4)                     // 4,194,304
#define CKQ4 ((long long)(WIN - SEQLEN) * KV_ROW / 4)       // 524,288
#define PREP_TOTAL (XQ4 + WQQ4 + WOQ4 + 2 * CKQ4)

__global__ __launch_bounds__(256) void prep_all(
    const float* __restrict__ x, __half* __restrict__ xh, __half* __restrict__ xl,
    const float* __restrict__ wq, __half* __restrict__ wqh,
    const float* __restrict__ wo, __half* __restrict__ woh,
    const float* __restrict__ in_ck, float* __restrict__ kcache,
    const float* __restrict__ in_cv, float* __restrict__ vcache)
{
    long long i = (long long)blockIdx.x * 256 + threadIdx.x;
    if (i < XQ4) {
        float4 v = ((const float4*)x)[i];
        float vv[4] = {v.x, v.y, v.z, v.w};
        union { unsigned long long u; __half h[4]; } H, L;
#pragma unroll
        for (int j = 0; j < 4; j++) {
            __half h = __float2half_rn(vv[j]);
            H.h[j] = h;
            L.h[j] = __float2half_rn(vv[j] - __half2float(h));
        }
        ((unsigned long long*)xh)[i] = H.u;
        ((unsigned long long*)xl)[i] = L.u;
    } else if (i < XQ4 + WQQ4) {
        long long k = i - XQ4;
        float4 v = ((const float4*)wq)[k];
        union { unsigned long long u; __half h[4]; } H;
        H.h[0] = __float2half_rn(v.x); H.h[1] = __float2half_rn(v.y);
        H.h[2] = __float2half_rn(v.z); H.h[3] = __float2half_rn(v.w);
        ((unsigned long long*)wqh)[k] = H.u;
    } else if (i < XQ4 + WQQ4 + WOQ4) {
        long long k = i - XQ4 - WQQ4;
        float4 v = ((const float4*)wo)[k];
        union { unsigned long long u; __half h[4]; } H;
        H.h[0] = __float2half_rn(v.x); H.h[1] = __float2half_rn(v.y);
        H.h[2] = __float2half_rn(v.z); H.h[3] = __float2half_rn(v.w);
        ((unsigned long long*)woh)[k] = H.u;
    } else if (i < XQ4 + WQQ4 + WOQ4 + CKQ4) {
        long long j = i - XQ4 - WQQ4 - WOQ4 + (long long)SEQLEN * KV_ROW / 4;
        ((float4*)kcache)[j] = ((const float4*)in_ck)[j];
    } else if (i < PREP_TOTAL) {
        long long j = i - XQ4 - WQQ4 - WOQ4 - CKQ4 + (long long)SEQLEN * KV_ROW / 4;
        ((float4*)vcache)[j] = ((const float4*)in_cv)[j];
    }
}

// ---------------- fp16 2-term mma.sync GEMM: C = A * B^T ---------------------
// CTA 128x128, 4 warps (2x2), warp tile 64x64. K = 4096, KC = 64.
// mode 0: plain fp32 store. mode 1: fused RoPE/scale/split QKV epilogue.
#define GK       4096
#define NCHUNK   (GK / 64)               // 64
#define PTILEB   (128 * 128)             // 16384 per part-tile
#define STAGEB   (3 * PTILEB)            // 49152
#define GEMM_SMEM (2 * STAGEB)           // 98304

__global__ __launch_bounds__(128, 2) void gemm_mma(
    const __half* __restrict__ Ah, const __half* __restrict__ Al,
    const __half* __restrict__ Bh, float* __restrict__ C, int N, int mode,
    const float* __restrict__ cosf_, const float* __restrict__ sinf_,
    float* __restrict__ kcache, float* __restrict__ vcache,
    __nv_bfloat16* __restrict__ qhi, __nv_bfloat16* __restrict__ qlo,
    __nv_bfloat16* __restrict__ khi, __nv_bfloat16* __restrict__ klo,
    __nv_bfloat16* __restrict__ vhi, __nv_bfloat16* __restrict__ vlo)
{
    extern __shared__ __align__(128) char smraw[];
    const uint32_t sb = (uint32_t)__cvta_generic_to_shared(smraw);

    const int tid = threadIdx.x;
    const int w   = tid >> 5;
    const int l   = tid & 31;
    const int wm  = w & 1;
    const int wn  = w >> 1;

    const size_t arow_g = (size_t)blockIdx.y * 128 * GK;
    const size_t brow_g = (size_t)blockIdx.x * 128 * GK;
    const char* gp[3] = { (const char*)(Ah + arow_g), (const char*)(Al + arow_g),
                          (const char*)(Bh + brow_g) };

    auto load_chunk = [&](int t, uint32_t st) {
        const size_t gk = (size_t)t * 128;
#pragma unroll
        for (int part = 0; part < 3; part++) {
#pragma unroll
            for (int j = 0; j < 8; j++) {
                int slot = tid + j * 128;
                int r = slot >> 3, c = slot & 7;
                uint32_t dc = (uint32_t)((c ^ (r & 7)) * 16);
                cp16(st + part * PTILEB + r * 128 + dc,
                     gp[part] + (size_t)r * (GK * 2) + gk + c * 16);
            }
        }
    };

    const int arow = wm * 64 + (l & 15);
    const uint32_t arb  = (uint32_t)(arow * 128);
    const int axor = arow & 7;
    const int ac0 = (l >> 4);
    const int l2 = l & 7, sel = l >> 3;
    const int brow = wn * 64 + (sel >> 1) * 8 + l2;
    const uint32_t brb  = (uint32_t)(brow * 128);
    const int bxor = brow & 7;
    const int bc0 = (sel & 1);

    float acc[4][8][4];
#pragma unroll
    for (int mt = 0; mt < 4; mt++)
#pragma unroll
        for (int nt = 0; nt < 8; nt++)
#pragma unroll
            for (int i = 0; i < 4; i++) acc[mt][nt][i] = 0.f;

    load_chunk(0, sb);
    asm volatile("cp.async.commit_group;" ::: "memory");

    for (int k = 0; k < NCHUNK; k++) {
        asm volatile("cp.async.wait_group 0;" ::: "memory");
        __syncthreads();
        if (k + 1 < NCHUNK) {
            load_chunk(k + 1, sb + ((k + 1) & 1) * STAGEB);
            asm volatile("cp.async.commit_group;" ::: "memory");
        }

        const uint32_t st = sb + (k & 1) * STAGEB;
#pragma unroll
        for (int ks = 0; ks < 4; ks++) {
            const uint32_t ach = (uint32_t)(((ks * 2 + ac0) ^ axor) * 16);
            const uint32_t bch = (uint32_t)(((ks * 2 + bc0) ^ bxor) * 16);

            uint32_t ah[4][4], bh[8][2];
#pragma unroll
            for (int mt = 0; mt < 4; mt++)
                ldm4(ah[mt][0], ah[mt][1], ah[mt][2], ah[mt][3],
                     st + arb + mt * 2048 + ach);
#pragma unroll
            for (int np = 0; np < 4; np++)
                ldm4(bh[2*np][0], bh[2*np][1], bh[2*np+1][0], bh[2*np+1][1],
                     st + 2 * PTILEB + brb + np * 2048 + bch);
#pragma unroll
            for (int mt = 0; mt < 4; mt++)
#pragma unroll
                for (int nt = 0; nt < 8; nt++)
                    mma_f16(acc[mt][nt], ah[mt], bh[nt]);

            uint32_t al[4][4];
#pragma unroll
            for (int mt = 0; mt < 4; mt++)
                ldm4(al[mt][0], al[mt][1], al[mt][2], al[mt][3],
                     st + PTILEB + arb + mt * 2048 + ach);
#pragma unroll
            for (int mt = 0; mt < 4; mt++)
#pragma unroll
                for (int nt = 0; nt < 8; nt++)
                    mma_f16(acc[mt][nt], al[mt], bh[nt]);
        }
    }

    const int crow = blockIdx.y * 128 + wm * 64 + (l >> 2);
    const int ccolbase = wn * 64 + (l & 3) * 2;

    if (mode == 0) {
        const int ccol = blockIdx.x * 128 + ccolbase;
#pragma unroll
        for (int mt = 0; mt < 4; mt++) {
#pragma unroll
            for (int nt = 0; nt < 8; nt++) {
                float* p0 = C + (size_t)(crow + mt * 16)     * N + ccol + nt * 8;
                float* p1 = C + (size_t)(crow + mt * 16 + 8) * N + ccol + nt * 8;
                *(float2*)p0 = make_float2(acc[mt][nt][0], acc[mt][nt][1]);
                *(float2*)p1 = make_float2(acc[mt][nt][2], acc[mt][nt][3]);
            }
        }
        return;
    }

    // ---- mode 1: fused QKV epilogue (one head per CTA column block) --------
    const int bx = blockIdx.x;
#pragma unroll
    for (int mt = 0; mt < 4; mt++) {
#pragma unroll
        for (int j = 0; j < 2; j++) {
            const int s = crow + mt * 16 + j * 8;
#pragma unroll
            for (int nt = 0; nt < 8; nt++) {
                float v0 = acc[mt][nt][j * 2 + 0];
                float v1 = acc[mt][nt][j * 2 + 1];
                const int d = ccolbase + nt * 8;
                if (bx < NH) {
                    const int f = d >> 1;
                    float c  = __ldg(cosf_ + s * 64 + f);
                    float sn = __ldg(sinf_ + s * 64 + f);
                    float o1 = (v0 * c - v1 * sn) * SCALE;
                    float o2 = (v0 * sn + v1 * c) * SCALE;
                    size_t o = ((size_t)bx * SEQLEN + s) * HD + d;
                    __nv_bfloat162 h2, l2v;
                    split2bf(o1, o2, h2, l2v);
                    *(__nv_bfloat162*)(qhi + o) = h2;
                    *(__nv_bfloat162*)(qlo + o) = l2v;
                } else if (bx < NH + NKV) {
                    const int kvh = bx - NH;
                    const int f = d >> 1;
                    float c  = __ldg(cosf_ + s * 64 + f);
                    float sn = __ldg(sinf_ + s * 64 + f);
                    float o1 = v0 * c - v1 * sn;
                    float o2 = v0 * sn + v1 * c;
                    *(float2*)(kcache + (size_t)s * KV_ROW + kvh * HD + d) =
                        make_float2(o1, o2);
                    size_t o = ((size_t)kvh * SEQLEN + s) * HD + d;
                    __nv_bfloat162 h2, l2v;
                    split2bf(o1, o2, h2, l2v);
                    *(__nv_bfloat162*)(khi + o) = h2;
                    *(__nv_bfloat162*)(klo + o) = l2v;
                } else {
                    const int kvh = bx - NH - NKV;
                    *(float2*)(vcache + (size_t)s * KV_ROW + kvh * HD + d) =
                        make_float2(v0, v1);
                    size_t o = ((size_t)kvh * SEQLEN + s) * HD + d;
                    __nv_bfloat162 h2, l2v;
                    split2bf(v0, v1, h2, l2v);
                    *(__nv_bfloat162*)(vhi + o) = h2;
                    *(__nv_bfloat162*)(vlo + o) = l2v;
                }
            }
        }
    }
}

// ---------------- tensor-core causal flash attention (double-buffered) ------
#define ASTRIDE 272
#define ATILE   (64 * ASTRIDE)
#define ABUF    (4 * ATILE)
#define ATTN_SMEM (2 * ABUF)

__global__ __launch_bounds__(256, 1) void attn_tc(
    const __nv_bfloat16* __restrict__ Qh, const __nv_bfloat16* __restrict__ Ql,
    const __nv_bfloat16* __restrict__ Kh, const __nv_bfloat16* __restrict__ Kl,
    const __nv_bfloat16* __restrict__ Vh, const __nv_bfloat16* __restrict__ Vl,
    __half* __restrict__ OH, __half* __restrict__ OL)
{
    extern __shared__ __align__(128) char smraw[];
    const uint32_t sb = (uint32_t)__cvta_generic_to_shared(smraw);
    const int tid = threadIdx.x, w = tid >> 5, l = tid & 31;
    const int qt  = (int)gridDim.x - 1 - (int)blockIdx.x;
    const int h   = blockIdx.y;
    const int kvh = h >> 2;

    uint32_t qh_[8][4], ql_[8][4];
    {
        const uint32_t aoff = sb + (uint32_t)((w * 16 + (l & 15)) * ASTRIDE
                                              + (l >> 4) * 16);
        for (int part = 0; part < 2; part++) {
            const __nv_bfloat16* src = part ? Ql : Qh;
            const char* g0 = (const char*)(src + ((size_t)h * SEQLEN + qt * 128) * HD);
            for (int i = tid; i < 2048; i += 256)
                cp16(sb + (uint32_t)((i >> 4) * ASTRIDE + (i & 15) * 16),
                     g0 + (size_t)i * 16);
            asm volatile("cp.async.commit_group;" ::: "memory");
            asm volatile("cp.async.wait_group 0;" ::: "memory");
            __syncthreads();
            uint32_t (*dst)[4] = part ? ql_ : qh_;
#pragma unroll
            for (int g = 0; g < 8; g++)
                ldm4(dst[g][0], dst[g][1], dst[g][2], dst[g][3], aoff + g * 32);
            __syncthreads();
        }
    }

    float o[16][4];
#pragma unroll
    for (int t = 0; t < 16; t++)
#pragma unroll
        for (int i = 0; i < 4; i++) o[t][i] = 0.f;
    float m0 = -1e30f, m1 = -1e30f, l0 = 0.f, l1 = 0.f;

    const int row0 = qt * 128 + w * 16 + (l >> 2);
    const int l2 = l & 7, sel = l >> 3;
    const int nkb = 2 * qt + 2;

    auto load_kv = [&](int kb, uint32_t bufbase) {
        const size_t gbase = (((size_t)kvh * SEQLEN + (size_t)kb * 64) * HD) * 2;
        for (int i = tid; i < 1024; i += 256) {
            uint32_t soff = (uint32_t)((i >> 4) * ASTRIDE + (i & 15) * 16);
            size_t goff = gbase + (size_t)i * 16;
            cp16(bufbase + 0 * ATILE + soff, (const char*)Kh + goff);
            cp16(bufbase + 1 * ATILE + soff, (const char*)Kl + goff);
            cp16(bufbase + 2 * ATILE + soff, (const char*)Vh + goff);
            cp16(bufbase + 3 * ATILE + soff, (const char*)Vl + goff);
        }
        asm volatile("cp.async.commit_group;" ::: "memory");
    };

    int buf = 0;
    load_kv(0, sb);

    for (int kb = 0; kb < nkb; kb++) {
        if (kb + 1 < nkb) {
            load_kv(kb + 1, sb + (buf ^ 1) * ABUF);
            asm volatile("cp.async.wait_group 1;" ::: "memory");
        } else {
            asm volatile("cp.async.wait_group 0;" ::: "memory");
        }
        __syncthreads();
        const uint32_t bbase = sb + buf * ABUF;

        float sc[8][4];
#pragma unroll
        for (int t = 0; t < 8; t++)
#pragma unroll
            for (int i = 0; i < 4; i++) sc[t][i] = 0.f;

#pragma unroll
        for (int g = 0; g < 8; g++) {
#pragma unroll
            for (int n16 = 0; n16 < 4; n16++) {
                uint32_t kaddr = bbase + (uint32_t)((n16 * 16 + (sel >> 1) * 8 + l2)
                                                    * ASTRIDE + (sel & 1) * 16 + g * 32);
                uint32_t bh[2][2], bl[2][2];
                ldm4(bh[0][0], bh[0][1], bh[1][0], bh[1][1], kaddr);
                ldm4(bl[0][0], bl[0][1], bl[1][0], bl[1][1], kaddr + ATILE);
#pragma unroll
                for (int j = 0; j < 2; j++) {
                    int t = n16 * 2 + j;
                    mma_bf16(sc[t], qh_[g], bh[j]);
                    mma_bf16(sc[t], ql_[g], bh[j]);
                    mma_bf16(sc[t], qh_[g], bl[j]);
                }
            }
        }

        if (kb >= 2 * qt) {
#pragma unroll
            for (int t = 0; t < 8; t++) {
                int col = kb * 64 + t * 8 + 2 * (l & 3);
                if (col     > row0)     sc[t][0] = -1e30f;
                if (col + 1 > row0)     sc[t][1] = -1e30f;
                if (col     > row0 + 8) sc[t][2] = -1e30f;
                if (col + 1 > row0 + 8) sc[t][3] = -1e30f;
            }
        }

        float r0m = -1e30f, r1m = -1e30f;
#pragma unroll
        for (int t = 0; t < 8; t++) {
            r0m = fmaxf(r0m, fmaxf(sc[t][0], sc[t][1]));
            r1m = fmaxf(r1m, fmaxf(sc[t][2], sc[t][3]));
        }
        r0m = fmaxf(r0m, __shfl_xor_sync(0xffffffffu, r0m, 1));
        r0m = fmaxf(r0m, __shfl_xor_sync(0xffffffffu, r0m, 2));
        r1m = fmaxf(r1m, __shfl_xor_sync(0xffffffffu, r1m, 1));
        r1m = fmaxf(r1m, __shfl_xor_sync(0xffffffffu, r1m, 2));
        float nm0 = fmaxf(m0, r0m), nm1 = fmaxf(m1, r1m);
        float a0 = __expf(m0 - nm0), a1 = __expf(m1 - nm1);

        float s0 = 0.f, s1 = 0.f;
#pragma unroll
        for (int t = 0; t < 8; t++) {
            sc[t][0] = __expf(sc[t][0] - nm0); s0 += sc[t][0];
            sc[t][1] = __expf(sc[t][1] - nm0); s0 += sc[t][1];
            sc[t][2] = __expf(sc[t][2] - nm1); s1 += sc[t][2];
            sc[t][3] = __expf(sc[t][3] - nm1); s1 += sc[t][3];
        }
        s0 += __shfl_xor_sync(0xffffffffu, s0, 1);
        s0 += __shfl_xor_sync(0xffffffffu, s0, 2);
        s1 += __shfl_xor_sync(0xffffffffu, s1, 1);
        s1 += __shfl_xor_sync(0xffffffffu, s1, 2);
        l0 = l0 * a0 + s0;
        l1 = l1 * a1 + s1;
        m0 = nm0; m1 = nm1;
#pragma unroll
        for (int t = 0; t < 16; t++) {
            o[t][0] *= a0; o[t][1] *= a0;
            o[t][2] *= a1; o[t][3] *= a1;
        }

#pragma unroll
        for (int g = 0; g < 4; g++) {
            uint32_t aph[4], apl[4];
            split2(sc[2*g][0],   sc[2*g][1],   aph[0], apl[0]);
            split2(sc[2*g][2],   sc[2*g][3],   aph[1], apl[1]);
            split2(sc[2*g+1][0], sc[2*g+1][1], aph[2], apl[2]);
            split2(sc[2*g+1][2], sc[2*g+1][3], aph[3], apl[3]);
#pragma unroll
            for (int n16 = 0; n16 < 8; n16++) {
                uint32_t vaddr = bbase + 2 * ATILE
                    + (uint32_t)((g * 16 + (l & 15)) * ASTRIDE
                                 + n16 * 32 + (l >> 4) * 16);
                uint32_t bvh[2][2], bvl[2][2];
                ldm4t(bvh[0][0], bvh[0][1], bvh[1][0], bvh[1][1], vaddr);
                ldm4t(bvl[0][0], bvl[0][1], bvl[1][0], bvl[1][1], vaddr + ATILE);
#pragma unroll
                for (int j = 0; j < 2; j++) {
                    int t = n16 * 2 + j;
                    mma_bf16(o[t], aph, bvh[j]);
                    mma_bf16(o[t], apl, bvh[j]);
                    mma_bf16(o[t], aph, bvl[j]);
                }
            }
        }
        __syncthreads();
        buf ^= 1;
    }

    float i0 = 1.f / l0, i1 = 1.f / l1;
    const int colb = h * HD + 2 * (l & 3);
#pragma unroll
    for (int t = 0; t < 16; t++) {
        {
            float v0 = o[t][0] * i0, v1 = o[t][1] * i0;
            __half h0 = __float2half_rn(v0), h1 = __float2half_rn(v1);
            __half e0 = __float2half_rn(v0 - __half2float(h0));
            __half e1 = __float2half_rn(v1 - __half2float(h1));
            size_t off = (size_t)row0 * DIM + colb + t * 8;
            *(__half2*)(OH + off) = __halves2half2(h0, h1);
            *(__half2*)(OL + off) = __halves2half2(e0, e1);
        }
        {
            float v0 = o[t][2] * i1, v1 = o[t][3] * i1;
            __half h0 = __float2half_rn(v0), h1 = __float2half_rn(v1);
            __half e0 = __float2half_rn(v0 - __half2float(h0));
            __half e1 = __float2half_rn(v1 - __half2float(h1));
            size_t off = (size_t)(row0 + 8) * DIM + colb + t * 8;
            *(__half2*)(OH + off) = __halves2half2(h0, h1);
            *(__half2*)(OL + off) = __halves2half2(e0, e1);
        }
    }
}

// ---------------- launch ----------------------------------------------------
extern "C" void kernel_launch(void* const* d_in, const int* in_sizes, int n_in,
                              void* d_out, int out_size)
{
    const float* x     = (const float*)d_in[0];
    const float* cosf_ = (const float*)d_in[1];
    const float* sinf_ = (const float*)d_in[2];
    const float* in_ck = (const float*)d_in[5];
    const float* in_cv = (const float*)d_in[6];
    const float* Wqkv  = (const float*)d_in[7];
    const float* Wo    = (const float*)d_in[8];

    float* out     = (float*)d_out;
    float* cache_k = out + (size_t)SEQLEN * DIM;
    float* cache_v = cache_k + (size_t)WIN * KV_ROW;

    __half *xh_p, *xl_p, *ah_p, *al_p, *wq_p, *wo_p;
    __nv_bfloat16 *qhi_p, *qlo_p, *khi_p, *klo_p, *vhi_p, *vlo_p;
    cudaGetSymbolAddress((void**)&xh_p,   g_xh);
    cudaGetSymbolAddress((void**)&xl_p,   g_xl);
    cudaGetSymbolAddress((void**)&ah_p,   g_ah);
    cudaGetSymbolAddress((void**)&al_p,   g_al);
    cudaGetSymbolAddress((void**)&wq_p,   g_wq);
    cudaGetSymbolAddress((void**)&wo_p,   g_wo);
    cudaGetSymbolAddress((void**)&qhi_p,  g_qhi);
    cudaGetSymbolAddress((void**)&qlo_p,  g_qlo);
    cudaGetSymbolAddress((void**)&khi_p,  g_khi);
    cudaGetSymbolAddress((void**)&klo_p,  g_klo);
    cudaGetSymbolAddress((void**)&vhi_p,  g_vhi);
    cudaGetSymbolAddress((void**)&vlo_p,  g_vlo);

    cudaFuncSetAttribute(gemm_mma, cudaFuncAttributeMaxDynamicSharedMemorySize,
                         GEMM_SMEM);
    cudaFuncSetAttribute(attn_tc, cudaFuncAttributeMaxDynamicSharedMemorySize,
                         ATTN_SMEM);

    // 0) one bandwidth-bound prep kernel: all converts + cache tail copies
    prep_all<<<(unsigned)((PREP_TOTAL + 255) / 256), 256>>>(
        x, xh_p, xl_p, Wqkv, wq_p, Wo, wo_p,
        in_ck, cache_k, in_cv, cache_v);

    // 1) QKV projection w/ fused RoPE/scale/cache/split epilogue (mode 1)
    gemm_mma<<<dim3(QKV_N / 128, SEQLEN / 128), 128, GEMM_SMEM>>>(
        xh_p, xl_p, wq_p, nullptr, QKV_N, 1,
        cosf_, sinf_, cache_k, cache_v,
        qhi_p, qlo_p, khi_p, klo_p, vhi_p, vlo_p);

    // 2) tensor-core causal flash attention, fp16 hi/lo epilogue
    attn_tc<<<dim3(SEQLEN / 128, NH), 256, ATTN_SMEM>>>(
        qhi_p, qlo_p, khi_p, klo_p, vhi_p, vlo_p, ah_p, al_p);

    // 3) output projection (mode 0, plain fp32 store)
    gemm_mma<<<dim3(DIM / 128, SEQLEN / 128), 128, GEMM_SMEM>>>(
        ah_p, al_p, wo_p, out, DIM, 0,
        nullptr, nullptr, nullptr, nullptr,
        nullptr, nullptr, nullptr, nullptr, nullptr, nullptr);
}

// round 15
// speedup vs baseline: 1.0735x; 1.0459x over previous
#include <cuda_runtime.h>
#include <cuda_bf16.h>
#include <cuda_fp16.h>
#include <cstdint>
#include <math.h>

#define SEQLEN 2048
#define DIM    4096
#define NH     32
#define HD     128
#define NKV    8
#define QKV_N  6144
#define KV_ROW 1024
#define WIN    4096
#define SCALE  0.08838834764831845f

// ---------------- scratch (device globals) ----------------------------------
__device__ __half g_xh [(size_t)SEQLEN * DIM];
__device__ __half g_xl [(size_t)SEQLEN * DIM];
__device__ __half g_ah [(size_t)SEQLEN * DIM];
__device__ __half g_al [(size_t)SEQLEN * DIM];
__device__ __half g_wq [(size_t)QKV_N * DIM];
__device__ __half g_wo [(size_t)DIM * DIM];
__device__ __nv_bfloat16 g_qhi[(size_t)NH  * SEQLEN * HD];
__device__ __nv_bfloat16 g_qlo[(size_t)NH  * SEQLEN * HD];
__device__ __nv_bfloat16 g_khi[(size_t)NKV * SEQLEN * HD];
__device__ __nv_bfloat16 g_klo[(size_t)NKV * SEQLEN * HD];
__device__ __half        g_vh [(size_t)NKV * SEQLEN * HD];   // V single fp16

// ---------------- common PTX helpers ----------------------------------------
__device__ __forceinline__ void cp16(uint32_t d, const void* g) {
    asm volatile("cp.async.cg.shared.global [%0], [%1], 16;\n"
                 :: "r"(d), "l"(__cvta_generic_to_global(g)) : "memory");
}
__device__ __forceinline__ void ldm4(uint32_t& r0, uint32_t& r1,
                                     uint32_t& r2, uint32_t& r3, uint32_t a) {
    asm volatile("ldmatrix.sync.aligned.m8n8.x4.shared.b16 {%0,%1,%2,%3}, [%4];"
                 : "=r"(r0), "=r"(r1), "=r"(r2), "=r"(r3) : "r"(a));
}
__device__ __forceinline__ void ldm4t(uint32_t& r0, uint32_t& r1,
                                      uint32_t& r2, uint32_t& r3, uint32_t a) {
    asm volatile("ldmatrix.sync.aligned.m8n8.x4.trans.shared.b16 {%0,%1,%2,%3}, [%4];"
                 : "=r"(r0), "=r"(r1), "=r"(r2), "=r"(r3) : "r"(a));
}
__device__ __forceinline__ void mma_bf16(float* c, const uint32_t* a,
                                         const uint32_t* b) {
    asm volatile(
        "mma.sync.aligned.m16n8k16.row.col.f32.bf16.bf16.f32 "
        "{%0,%1,%2,%3}, {%4,%5,%6,%7}, {%8,%9}, {%0,%1,%2,%3};"
        : "+f"(c[0]), "+f"(c[1]), "+f"(c[2]), "+f"(c[3])
        : "r"(a[0]), "r"(a[1]), "r"(a[2]), "r"(a[3]), "r"(b[0]), "r"(b[1]));
}
__device__ __forceinline__ void mma_f16(float* c, const uint32_t* a,
                                        const uint32_t* b) {
    asm volatile(
        "mma.sync.aligned.m16n8k16.row.col.f32.f16.f16.f32 "
        "{%0,%1,%2,%3}, {%4,%5,%6,%7}, {%8,%9}, {%0,%1,%2,%3};"
        : "+f"(c[0]), "+f"(c[1]), "+f"(c[2]), "+f"(c[3])
        : "r"(a[0]), "r"(a[1]), "r"(a[2]), "r"(a[3]), "r"(b[0]), "r"(b[1]));
}
__device__ __forceinline__ void split2h(float x, float y, uint32_t& hi, uint32_t& lo) {
    __half2 h = __floats2half2_rn(x, y);
    float rx = x - __half2float(__low2half(h));
    float ry = y - __half2float(__high2half(h));
    __half2 r = __floats2half2_rn(rx, ry);
    hi = *(uint32_t*)&h; lo = *(uint32_t*)&r;
}
__device__ __forceinline__ void split2bf(float x, float y,
                                         __nv_bfloat162& h2, __nv_bfloat162& l2) {
    h2 = __floats2bfloat162_rn(x, y);
    float rx = x - __bfloat162float(h2.x);
    float ry = y - __bfloat162float(h2.y);
    l2 = __floats2bfloat162_rn(rx, ry);
}

// ---------------- single prep kernel: all converts + cache tail copies ------
#define XQ4  ((long long)SEQLEN * DIM / 4)
#define WQQ4 ((long long)QKV_N * DIM / 4)
#define WOQ4 ((long long)DIM * DIM / 4)
#define CKQ4 ((long long)(WIN - SEQLEN) * KV_ROW / 4)
#define PREP_TOTAL (XQ4 + WQQ4 + WOQ4 + 2 * CKQ4)

__global__ __launch_bounds__(256) void prep_all(
    const float* __restrict__ x, __half* __restrict__ xh, __half* __restrict__ xl,
    const float* __restrict__ wq, __half* __restrict__ wqh,
    const float* __restrict__ wo, __half* __restrict__ woh,
    const float* __restrict__ in_ck, float* __restrict__ kcache,
    const float* __restrict__ in_cv, float* __restrict__ vcache)
{
    long long i = (long long)blockIdx.x * 256 + threadIdx.x;
    if (i < XQ4) {
        float4 v = ((const float4*)x)[i];
        float vv[4] = {v.x, v.y, v.z, v.w};
        union { unsigned long long u; __half h[4]; } H, L;
#pragma unroll
        for (int j = 0; j < 4; j++) {
            __half h = __float2half_rn(vv[j]);
            H.h[j] = h;
            L.h[j] = __float2half_rn(vv[j] - __half2float(h));
        }
        ((unsigned long long*)xh)[i] = H.u;
        ((unsigned long long*)xl)[i] = L.u;
    } else if (i < XQ4 + WQQ4) {
        long long k = i - XQ4;
        float4 v = ((const float4*)wq)[k];
        union { unsigned long long u; __half h[4]; } H;
        H.h[0] = __float2half_rn(v.x); H.h[1] = __float2half_rn(v.y);
        H.h[2] = __float2half_rn(v.z); H.h[3] = __float2half_rn(v.w);
        ((unsigned long long*)wqh)[k] = H.u;
    } else if (i < XQ4 + WQQ4 + WOQ4) {
        long long k = i - XQ4 - WQQ4;
        float4 v = ((const float4*)wo)[k];
        union { unsigned long long u; __half h[4]; } H;
        H.h[0] = __float2half_rn(v.x); H.h[1] = __float2half_rn(v.y);
        H.h[2] = __float2half_rn(v.z); H.h[3] = __float2half_rn(v.w);
        ((unsigned long long*)woh)[k] = H.u;
    } else if (i < XQ4 + WQQ4 + WOQ4 + CKQ4) {
        long long j = i - XQ4 - WQQ4 - WOQ4 + (long long)SEQLEN * KV_ROW / 4;
        ((float4*)kcache)[j] = ((const float4*)in_ck)[j];
    } else if (i < PREP_TOTAL) {
        long long j = i - XQ4 - WQQ4 - WOQ4 - CKQ4 + (long long)SEQLEN * KV_ROW / 4;
        ((float4*)vcache)[j] = ((const float4*)in_cv)[j];
    }
}

// ---------------- fp16 2-term mma.sync GEMM: C = A * B^T ---------------------
#define GK       4096
#define NCHUNK   (GK / 64)
#define PTILEB   (128 * 128)
#define STAGEB   (3 * PTILEB)
#define GEMM_SMEM (2 * STAGEB)

__global__ __launch_bounds__(128, 2) void gemm_mma(
    const __half* __restrict__ Ah, const __half* __restrict__ Al,
    const __half* __restrict__ Bh, float* __restrict__ C, int N, int mode,
    const float* __restrict__ cosf_, const float* __restrict__ sinf_,
    float* __restrict__ kcache, float* __restrict__ vcache,
    __nv_bfloat16* __restrict__ qhi, __nv_bfloat16* __restrict__ qlo,
    __nv_bfloat16* __restrict__ khi, __nv_bfloat16* __restrict__ klo,
    __half* __restrict__ vh)
{
    extern __shared__ __align__(128) char smraw[];
    const uint32_t sb = (uint32_t)__cvta_generic_to_shared(smraw);

    const int tid = threadIdx.x;
    const int w   = tid >> 5;
    const int l   = tid & 31;
    const int wm  = w & 1;
    const int wn  = w >> 1;

    const size_t arow_g = (size_t)blockIdx.y * 128 * GK;
    const size_t brow_g = (size_t)blockIdx.x * 128 * GK;
    const char* gp[3] = { (const char*)(Ah + arow_g), (const char*)(Al + arow_g),
                          (const char*)(Bh + brow_g) };

    auto load_chunk = [&](int t, uint32_t st) {
        const size_t gk = (size_t)t * 128;
#pragma unroll
        for (int part = 0; part < 3; part++) {
#pragma unroll
            for (int j = 0; j < 8; j++) {
                int slot = tid + j * 128;
                int r = slot >> 3, c = slot & 7;
                uint32_t dc = (uint32_t)((c ^ (r & 7)) * 16);
                cp16(st + part * PTILEB + r * 128 + dc,
                     gp[part] + (size_t)r * (GK * 2) + gk + c * 16);
            }
        }
    };

    const int arow = wm * 64 + (l & 15);
    const uint32_t arb  = (uint32_t)(arow * 128);
    const int axor = arow & 7;
    const int ac0 = (l >> 4);
    const int l2 = l & 7, sel = l >> 3;
    const int brow = wn * 64 + (sel >> 1) * 8 + l2;
    const uint32_t brb  = (uint32_t)(brow * 128);
    const int bxor = brow & 7;
    const int bc0 = (sel & 1);

    float acc[4][8][4];
#pragma unroll
    for (int mt = 0; mt < 4; mt++)
#pragma unroll
        for (int nt = 0; nt < 8; nt++)
#pragma unroll
            for (int i = 0; i < 4; i++) acc[mt][nt][i] = 0.f;

    load_chunk(0, sb);
    asm volatile("cp.async.commit_group;" ::: "memory");

    for (int k = 0; k < NCHUNK; k++) {
        asm volatile("cp.async.wait_group 0;" ::: "memory");
        __syncthreads();
        if (k + 1 < NCHUNK) {
            load_chunk(k + 1, sb + ((k + 1) & 1) * STAGEB);
            asm volatile("cp.async.commit_group;" ::: "memory");
        }

        const uint32_t st = sb + (k & 1) * STAGEB;
#pragma unroll
        for (int ks = 0; ks < 4; ks++) {
            const uint32_t ach = (uint32_t)(((ks * 2 + ac0) ^ axor) * 16);
            const uint32_t bch = (uint32_t)(((ks * 2 + bc0) ^ bxor) * 16);

            uint32_t ah[4][4], bh[8][2];
#pragma unroll
            for (int mt = 0; mt < 4; mt++)
                ldm4(ah[mt][0], ah[mt][1], ah[mt][2], ah[mt][3],
                     st + arb + mt * 2048 + ach);
#pragma unroll
            for (int np = 0; np < 4; np++)
                ldm4(bh[2*np][0], bh[2*np][1], bh[2*np+1][0], bh[2*np+1][1],
                     st + 2 * PTILEB + brb + np * 2048 + bch);
#pragma unroll
            for (int mt = 0; mt < 4; mt++)
#pragma unroll
                for (int nt = 0; nt < 8; nt++)
                    mma_f16(acc[mt][nt], ah[mt], bh[nt]);

            uint32_t al[4][4];
#pragma unroll
            for (int mt = 0; mt < 4; mt++)
                ldm4(al[mt][0], al[mt][1], al[mt][2], al[mt][3],
                     st + PTILEB + arb + mt * 2048 + ach);
#pragma unroll
            for (int mt = 0; mt < 4; mt++)
#pragma unroll
                for (int nt = 0; nt < 8; nt++)
                    mma_f16(acc[mt][nt], al[mt], bh[nt]);
        }
    }

    const int crow = blockIdx.y * 128 + wm * 64 + (l >> 2);
    const int ccolbase = wn * 64 + (l & 3) * 2;

    if (mode == 0) {
        const int ccol = blockIdx.x * 128 + ccolbase;
#pragma unroll
        for (int mt = 0; mt < 4; mt++) {
#pragma unroll
            for (int nt = 0; nt < 8; nt++) {
                float* p0 = C + (size_t)(crow + mt * 16)     * N + ccol + nt * 8;
                float* p1 = C + (size_t)(crow + mt * 16 + 8) * N + ccol + nt * 8;
                *(float2*)p0 = make_float2(acc[mt][nt][0], acc[mt][nt][1]);
                *(float2*)p1 = make_float2(acc[mt][nt][2], acc[mt][nt][3]);
            }
        }
        return;
    }

    // ---- mode 1: fused QKV epilogue (one head per CTA column block) --------
    const int bx = blockIdx.x;
#pragma unroll
    for (int mt = 0; mt < 4; mt++) {
#pragma unroll
        for (int j = 0; j < 2; j++) {
            const int s = crow + mt * 16 + j * 8;
#pragma unroll
            for (int nt = 0; nt < 8; nt++) {
                float v0 = acc[mt][nt][j * 2 + 0];
                float v1 = acc[mt][nt][j * 2 + 1];
                const int d = ccolbase + nt * 8;
                if (bx < NH) {
                    const int f = d >> 1;
                    float c  = __ldg(cosf_ + s * 64 + f);
                    float sn = __ldg(sinf_ + s * 64 + f);
                    float o1 = (v0 * c - v1 * sn) * SCALE;
                    float o2 = (v0 * sn + v1 * c) * SCALE;
                    size_t o = ((size_t)bx * SEQLEN + s) * HD + d;
                    __nv_bfloat162 h2, l2v;
                    split2bf(o1, o2, h2, l2v);
                    *(__nv_bfloat162*)(qhi + o) = h2;
                    *(__nv_bfloat162*)(qlo + o) = l2v;
                } else if (bx < NH + NKV) {
                    const int kvh = bx - NH;
                    const int f = d >> 1;
                    float c  = __ldg(cosf_ + s * 64 + f);
                    float sn = __ldg(sinf_ + s * 64 + f);
                    float o1 = v0 * c - v1 * sn;
                    float o2 = v0 * sn + v1 * c;
                    *(float2*)(kcache + (size_t)s * KV_ROW + kvh * HD + d) =
                        make_float2(o1, o2);
                    size_t o = ((size_t)kvh * SEQLEN + s) * HD + d;
                    __nv_bfloat162 h2, l2v;
                    split2bf(o1, o2, h2, l2v);
                    *(__nv_bfloat162*)(khi + o) = h2;
                    *(__nv_bfloat162*)(klo + o) = l2v;
                } else {
                    const int kvh = bx - NH - NKV;
                    *(float2*)(vcache + (size_t)s * KV_ROW + kvh * HD + d) =
                        make_float2(v0, v1);
                    size_t o = ((size_t)kvh * SEQLEN + s) * HD + d;
                    *(__half2*)(vh + o) = __floats2half2_rn(v0, v1);
                }
            }
        }
    }
}

// ---------------- tensor-core causal flash attention (double-buffered) ------
// K: bf16 hi/lo 3-term; V: single fp16, P split fp16 hi/lo (2-term PV).
#define ASTRIDE 272
#define ATILE   (64 * ASTRIDE)
#define ABUF    (3 * ATILE)              // Khi | Klo | Vh
#define ATTN_SMEM (2 * ABUF)             // 104448

__global__ __launch_bounds__(256, 1) void attn_tc(
    const __nv_bfloat16* __restrict__ Qh, const __nv_bfloat16* __restrict__ Ql,
    const __nv_bfloat16* __restrict__ Kh, const __nv_bfloat16* __restrict__ Kl,
    const __half* __restrict__ Vh,
    __half* __restrict__ OH, __half* __restrict__ OL)
{
    extern __shared__ __align__(128) char smraw[];
    const uint32_t sb = (uint32_t)__cvta_generic_to_shared(smraw);
    const int tid = threadIdx.x, w = tid >> 5, l = tid & 31;
    const int qt  = (int)gridDim.x - 1 - (int)blockIdx.x;
    const int h   = blockIdx.y;
    const int kvh = h >> 2;

    uint32_t qh_[8][4], ql_[8][4];
    {
        const uint32_t aoff = sb + (uint32_t)((w * 16 + (l & 15)) * ASTRIDE
                                              + (l >> 4) * 16);
        for (int part = 0; part < 2; part++) {
            const __nv_bfloat16* src = part ? Ql : Qh;
            const char* g0 = (const char*)(src + ((size_t)h * SEQLEN + qt * 128) * HD);
            for (int i = tid; i < 2048; i += 256)
                cp16(sb + (uint32_t)((i >> 4) * ASTRIDE + (i & 15) * 16),
                     g0 + (size_t)i * 16);
            asm volatile("cp.async.commit_group;" ::: "memory");
            asm volatile("cp.async.wait_group 0;" ::: "memory");
            __syncthreads();
            uint32_t (*dst)[4] = part ? ql_ : qh_;
#pragma unroll
            for (int g = 0; g < 8; g++)
                ldm4(dst[g][0], dst[g][1], dst[g][2], dst[g][3], aoff + g * 32);
            __syncthreads();
        }
    }

    float o[16][4];
#pragma unroll
    for (int t = 0; t < 16; t++)
#pragma unroll
        for (int i = 0; i < 4; i++) o[t][i] = 0.f;
    float m0 = -1e30f, m1 = -1e30f, l0 = 0.f, l1 = 0.f;

    const int row0 = qt * 128 + w * 16 + (l >> 2);
    const int l2 = l & 7, sel = l >> 3;
    const int nkb = 2 * qt + 2;

    auto load_kv = [&](int kb, uint32_t bufbase) {
        const size_t gbase = (((size_t)kvh * SEQLEN + (size_t)kb * 64) * HD) * 2;
        for (int i = tid; i < 1024; i += 256) {
            uint32_t soff = (uint32_t)((i >> 4) * ASTRIDE + (i & 15) * 16);
            size_t goff = gbase + (size_t)i * 16;
            cp16(bufbase + 0 * ATILE + soff, (const char*)Kh + goff);
            cp16(bufbase + 1 * ATILE + soff, (const char*)Kl + goff);
            cp16(bufbase + 2 * ATILE + soff, (const char*)Vh + goff);
        }
        asm volatile("cp.async.commit_group;" ::: "memory");
    };

    int buf = 0;
    load_kv(0, sb);

    for (int kb = 0; kb < nkb; kb++) {
        if (kb + 1 < nkb) {
            load_kv(kb + 1, sb + (buf ^ 1) * ABUF);
            asm volatile("cp.async.wait_group 1;" ::: "memory");
        } else {
            asm volatile("cp.async.wait_group 0;" ::: "memory");
        }
        __syncthreads();
        const uint32_t bbase = sb + buf * ABUF;

        float sc[8][4];
#pragma unroll
        for (int t = 0; t < 8; t++)
#pragma unroll
            for (int i = 0; i < 4; i++) sc[t][i] = 0.f;

#pragma unroll
        for (int g = 0; g < 8; g++) {
#pragma unroll
            for (int n16 = 0; n16 < 4; n16++) {
                uint32_t kaddr = bbase + (uint32_t)((n16 * 16 + (sel >> 1) * 8 + l2)
                                                    * ASTRIDE + (sel & 1) * 16 + g * 32);
                uint32_t bh[2][2], bl[2][2];
                ldm4(bh[0][0], bh[0][1], bh[1][0], bh[1][1], kaddr);
                ldm4(bl[0][0], bl[0][1], bl[1][0], bl[1][1], kaddr + ATILE);
#pragma unroll
                for (int j = 0; j < 2; j++) {
                    int t = n16 * 2 + j;
                    mma_bf16(sc[t], qh_[g], bh[j]);
                    mma_bf16(sc[t], ql_[g], bh[j]);
                    mma_bf16(sc[t], qh_[g], bl[j]);
                }
            }
        }

        if (kb >= 2 * qt) {
#pragma unroll
            for (int t = 0; t < 8; t++) {
                int col = kb * 64 + t * 8 + 2 * (l & 3);
                if (col     > row0)     sc[t][0] = -1e30f;
                if (col + 1 > row0)     sc[t][1] = -1e30f;
                if (col     > row0 + 8) sc[t][2] = -1e30f;
                if (col + 1 > row0 + 8) sc[t][3] = -1e30f;
            }
        }

        float r0m = -1e30f, r1m = -1e30f;
#pragma unroll
        for (int t = 0; t < 8; t++) {
            r0m = fmaxf(r0m, fmaxf(sc[t][0], sc[t][1]));
            r1m = fmaxf(r1m, fmaxf(sc[t][2], sc[t][3]));
        }
        r0m = fmaxf(r0m, __shfl_xor_sync(0xffffffffu, r0m, 1));
        r0m = fmaxf(r0m, __shfl_xor_sync(0xffffffffu, r0m, 2));
        r1m = fmaxf(r1m, __shfl_xor_sync(0xffffffffu, r1m, 1));
        r1m = fmaxf(r1m, __shfl_xor_sync(0xffffffffu, r1m, 2));
        float nm0 = fmaxf(m0, r0m), nm1 = fmaxf(m1, r1m);
        float a0 = __expf(m0 - nm0), a1 = __expf(m1 - nm1);

        float s0 = 0.f, s1 = 0.f;
#pragma unroll
        for (int t = 0; t < 8; t++) {
            sc[t][0] = __expf(sc[t][0] - nm0); s0 += sc[t][0];
            sc[t][1] = __expf(sc[t][1] - nm0); s0 += sc[t][1];
            sc[t][2] = __expf(sc[t][2] - nm1); s1 += sc[t][2];
            sc[t][3] = __expf(sc[t][3] - nm1); s1 += sc[t][3];
        }
        s0 += __shfl_xor_sync(0xffffffffu, s0, 1);
        s0 += __shfl_xor_sync(0xffffffffu, s0, 2);
        s1 += __shfl_xor_sync(0xffffffffu, s1, 1);
        s1 += __shfl_xor_sync(0xffffffffu, s1, 2);
        l0 = l0 * a0 + s0;
        l1 = l1 * a1 + s1;
        m0 = nm0; m1 = nm1;
#pragma unroll
        for (int t = 0; t < 16; t++) {
            o[t][0] *= a0; o[t][1] *= a0;
            o[t][2] *= a1; o[t][3] *= a1;
        }

        // ---- O += P V : P fp16 hi/lo 2-term, V single fp16 ------------------
#pragma unroll
        for (int g = 0; g < 4; g++) {
            uint32_t aph[4], apl[4];
            split2h(sc[2*g][0],   sc[2*g][1],   aph[0], apl[0]);
            split2h(sc[2*g][2],   sc[2*g][3],   aph[1], apl[1]);
            split2h(sc[2*g+1][0], sc[2*g+1][1], aph[2], apl[2]);
            split2h(sc[2*g+1][2], sc[2*g+1][3], aph[3], apl[3]);
#pragma unroll
            for (int n16 = 0; n16 < 8; n16++) {
                uint32_t vaddr = bbase + 2 * ATILE
                    + (uint32_t)((g * 16 + (l & 15)) * ASTRIDE
                                 + n16 * 32 + (l >> 4) * 16);
                uint32_t bvh[2][2];
                ldm4t(bvh[0][0], bvh[0][1], bvh[1][0], bvh[1][1], vaddr);
#pragma unroll
                for (int j = 0; j < 2; j++) {
                    int t = n16 * 2 + j;
                    mma_f16(o[t], aph, bvh[j]);
                    mma_f16(o[t], apl, bvh[j]);
                }
            }
        }
        __syncthreads();
        buf ^= 1;
    }

    float i0 = 1.f / l0, i1 = 1.f / l1;
    const int colb = h * HD + 2 * (l & 3);
#pragma unroll
    for (int t = 0; t < 16; t++) {
        {
            float v0 = o[t][0] * i0, v1 = o[t][1] * i0;
            __half h0 = __float2half_rn(v0), h1 = __float2half_rn(v1);
            __half e0 = __float2half_rn(v0 - __half2float(h0));
            __half e1 = __float2half_rn(v1 - __half2float(h1));
            size_t off = (size_t)row0 * DIM + colb + t * 8;
            *(__half2*)(OH + off) = __halves2half2(h0, h1);
            *(__half2*)(OL + off) = __halves2half2(e0, e1);
        }
        {
            float v0 = o[t][2] * i1, v1 = o[t][3] * i1;
            __half h0 = __float2half_rn(v0), h1 = __float2half_rn(v1);
            __half e0 = __float2half_rn(v0 - __half2float(h0));
            __half e1 = __float2half_rn(v1 - __half2float(h1));
            size_t off = (size_t)(row0 + 8) * DIM + colb + t * 8;
            *(__half2*)(OH + off) = __halves2half2(h0, h1);
            *(__half2*)(OL + off) = __halves2half2(e0, e1);
        }
    }
}

// ---------------- launch ----------------------------------------------------
extern "C" void kernel_launch(void* const* d_in, const int* in_sizes, int n_in,
                              void* d_out, int out_size)
{
    const float* x     = (const float*)d_in[0];
    const float* cosf_ = (const float*)d_in[1];
    const float* sinf_ = (const float*)d_in[2];
    const float* in_ck = (const float*)d_in[5];
    const float* in_cv = (const float*)d_in[6];
    const float* Wqkv  = (const float*)d_in[7];
    const float* Wo    = (const float*)d_in[8];

    float* out     = (float*)d_out;
    float* cache_k = out + (size_t)SEQLEN * DIM;
    float* cache_v = cache_k + (size_t)WIN * KV_ROW;

    __half *xh_p, *xl_p, *ah_p, *al_p, *wq_p, *wo_p, *vh_p;
    __nv_bfloat16 *qhi_p, *qlo_p, *khi_p, *klo_p;
    cudaGetSymbolAddress((void**)&xh_p,   g_xh);
    cudaGetSymbolAddress((void**)&xl_p,   g_xl);
    cudaGetSymbolAddress((void**)&ah_p,   g_ah);
    cudaGetSymbolAddress((void**)&al_p,   g_al);
    cudaGetSymbolAddress((void**)&wq_p,   g_wq);
    cudaGetSymbolAddress((void**)&wo_p,   g_wo);
    cudaGetSymbolAddress((void**)&vh_p,   g_vh);
    cudaGetSymbolAddress((void**)&qhi_p,  g_qhi);
    cudaGetSymbolAddress((void**)&qlo_p,  g_qlo);
    cudaGetSymbolAddress((void**)&khi_p,  g_khi);
    cudaGetSymbolAddress((void**)&klo_p,  g_klo);

    cudaFuncSetAttribute(gemm_mma, cudaFuncAttributeMaxDynamicSharedMemorySize,
                         GEMM_SMEM);
    cudaFuncSetAttribute(attn_tc, cudaFuncAttributeMaxDynamicSharedMemorySize,
                         ATTN_SMEM);

    // 0) one bandwidth-bound prep kernel
    prep_all<<<(unsigned)((PREP_TOTAL + 255) / 256), 256>>>(
        x, xh_p, xl_p, Wqkv, wq_p, Wo, wo_p,
        in_ck, cache_k, in_cv, cache_v);

    // 1) QKV projection w/ fused RoPE/scale/cache/split epilogue (mode 1)
    gemm_mma<<<dim3(QKV_N / 128, SEQLEN / 128), 128, GEMM_SMEM>>>(
        xh_p, xl_p, wq_p, nullptr, QKV_N, 1,
        cosf_, sinf_, cache_k, cache_v,
        qhi_p, qlo_p, khi_p, klo_p, vh_p);

    // 2) tensor-core causal flash attention (V fp16 2-term PV)
    attn_tc<<<dim3(SEQLEN / 128, NH), 256, ATTN_SMEM>>>(
        qhi_p, qlo_p, khi_p, klo_p, vh_p, ah_p, al_p);

    // 3) output projection (mode 0, plain fp32 store)
    gemm_mma<<<dim3(DIM / 128, SEQLEN / 128), 128, GEMM_SMEM>>>(
        ah_p, al_p, wo_p, out, DIM, 0,
        nullptr, nullptr, nullptr, nullptr,
        nullptr, nullptr, nullptr, nullptr, nullptr);
}

// round 16
// speedup vs baseline: 1.2127x; 1.1296x over previous
#include <cuda_runtime.h>
#include <cuda_bf16.h>
#include <cuda_fp16.h>
#include <cstdint>
#include <math.h>

#define SEQLEN 2048
#define DIM    4096
#define NH     32
#define HD     128
#define NKV    8
#define QKV_N  6144
#define KV_ROW 1024
#define WIN    4096
#define SCALE  0.08838834764831845f

// ---------------- scratch (device globals) ----------------------------------
__device__ __half g_xh [(size_t)SEQLEN * DIM];
__device__ __half g_xl [(size_t)SEQLEN * DIM];
__device__ __half g_ah [(size_t)SEQLEN * DIM];        // attn out, single fp16
__device__ __half g_wq [(size_t)QKV_N * DIM];
__device__ __half g_wo [(size_t)DIM * DIM];
__device__ __nv_bfloat16 g_qhi[(size_t)NH  * SEQLEN * HD];
__device__ __nv_bfloat16 g_qlo[(size_t)NH  * SEQLEN * HD];
__device__ __nv_bfloat16 g_khi[(size_t)NKV * SEQLEN * HD];
__device__ __nv_bfloat16 g_klo[(size_t)NKV * SEQLEN * HD];
__device__ __half        g_vh [(size_t)NKV * SEQLEN * HD];

// ---------------- common PTX helpers ----------------------------------------
__device__ __forceinline__ void cp16(uint32_t d, const void* g) {
    asm volatile("cp.async.cg.shared.global [%0], [%1], 16;\n"
                 :: "r"(d), "l"(__cvta_generic_to_global(g)) : "memory");
}
__device__ __forceinline__ void ldm4(uint32_t& r0, uint32_t& r1,
                                     uint32_t& r2, uint32_t& r3, uint32_t a) {
    asm volatile("ldmatrix.sync.aligned.m8n8.x4.shared.b16 {%0,%1,%2,%3}, [%4];"
                 : "=r"(r0), "=r"(r1), "=r"(r2), "=r"(r3) : "r"(a));
}
__device__ __forceinline__ void ldm4t(uint32_t& r0, uint32_t& r1,
                                      uint32_t& r2, uint32_t& r3, uint32_t a) {
    asm volatile("ldmatrix.sync.aligned.m8n8.x4.trans.shared.b16 {%0,%1,%2,%3}, [%4];"
                 : "=r"(r0), "=r"(r1), "=r"(r2), "=r"(r3) : "r"(a));
}
__device__ __forceinline__ void mma_bf16(float* c, const uint32_t* a,
                                         const uint32_t* b) {
    asm volatile(
        "mma.sync.aligned.m16n8k16.row.col.f32.bf16.bf16.f32 "
        "{%0,%1,%2,%3}, {%4,%5,%6,%7}, {%8,%9}, {%0,%1,%2,%3};"
        : "+f"(c[0]), "+f"(c[1]), "+f"(c[2]), "+f"(c[3])
        : "r"(a[0]), "r"(a[1]), "r"(a[2]), "r"(a[3]), "r"(b[0]), "r"(b[1]));
}
__device__ __forceinline__ void mma_f16(float* c, const uint32_t* a,
                                        const uint32_t* b) {
    asm volatile(
        "mma.sync.aligned.m16n8k16.row.col.f32.f16.f16.f32 "
        "{%0,%1,%2,%3}, {%4,%5,%6,%7}, {%8,%9}, {%0,%1,%2,%3};"
        : "+f"(c[0]), "+f"(c[1]), "+f"(c[2]), "+f"(c[3])
        : "r"(a[0]), "r"(a[1]), "r"(a[2]), "r"(a[3]), "r"(b[0]), "r"(b[1]));
}
__device__ __forceinline__ void split2h(float x, float y, uint32_t& hi, uint32_t& lo) {
    __half2 h = __floats2half2_rn(x, y);
    float rx = x - __half2float(__low2half(h));
    float ry = y - __half2float(__high2half(h));
    __half2 r = __floats2half2_rn(rx, ry);
    hi = *(uint32_t*)&h; lo = *(uint32_t*)&r;
}
__device__ __forceinline__ void split2bf(float x, float y,
                                         __nv_bfloat162& h2, __nv_bfloat162& l2) {
    h2 = __floats2bfloat162_rn(x, y);
    float rx = x - __bfloat162float(h2.x);
    float ry = y - __bfloat162float(h2.y);
    l2 = __floats2bfloat162_rn(rx, ry);
}

// ---------------- single prep kernel: all converts + cache tail copies ------
#define XQ4  ((long long)SEQLEN * DIM / 4)
#define WQQ4 ((long long)QKV_N * DIM / 4)
#define WOQ4 ((long long)DIM * DIM / 4)
#define CKQ4 ((long long)(WIN - SEQLEN) * KV_ROW / 4)
#define PREP_TOTAL (XQ4 + WQQ4 + WOQ4 + 2 * CKQ4)

__global__ __launch_bounds__(256) void prep_all(
    const float* __restrict__ x, __half* __restrict__ xh, __half* __restrict__ xl,
    const float* __restrict__ wq, __half* __restrict__ wqh,
    const float* __restrict__ wo, __half* __restrict__ woh,
    const float* __restrict__ in_ck, float* __restrict__ kcache,
    const float* __restrict__ in_cv, float* __restrict__ vcache)
{
    long long i = (long long)blockIdx.x * 256 + threadIdx.x;
    if (i < XQ4) {
        float4 v = ((const float4*)x)[i];
        float vv[4] = {v.x, v.y, v.z, v.w};
        union { unsigned long long u; __half h[4]; } H, L;
#pragma unroll
        for (int j = 0; j < 4; j++) {
            __half h = __float2half_rn(vv[j]);
            H.h[j] = h;
            L.h[j] = __float2half_rn(vv[j] - __half2float(h));
        }
        ((unsigned long long*)xh)[i] = H.u;
        ((unsigned long long*)xl)[i] = L.u;
    } else if (i < XQ4 + WQQ4) {
        long long k = i - XQ4;
        float4 v = ((const float4*)wq)[k];
        union { unsigned long long u; __half h[4]; } H;
        H.h[0] = __float2half_rn(v.x); H.h[1] = __float2half_rn(v.y);
        H.h[2] = __float2half_rn(v.z); H.h[3] = __float2half_rn(v.w);
        ((unsigned long long*)wqh)[k] = H.u;
    } else if (i < XQ4 + WQQ4 + WOQ4) {
        long long k = i - XQ4 - WQQ4;
        float4 v = ((const float4*)wo)[k];
        union { unsigned long long u; __half h[4]; } H;
        H.h[0] = __float2half_rn(v.x); H.h[1] = __float2half_rn(v.y);
        H.h[2] = __float2half_rn(v.z); H.h[3] = __float2half_rn(v.w);
        ((unsigned long long*)woh)[k] = H.u;
    } else if (i < XQ4 + WQQ4 + WOQ4 + CKQ4) {
        long long j = i - XQ4 - WQQ4 - WOQ4 + (long long)SEQLEN * KV_ROW / 4;
        ((float4*)kcache)[j] = ((const float4*)in_ck)[j];
    } else if (i < PREP_TOTAL) {
        long long j = i - XQ4 - WQQ4 - WOQ4 - CKQ4 + (long long)SEQLEN * KV_ROW / 4;
        ((float4*)vcache)[j] = ((const float4*)in_cv)[j];
    }
}

// ---------------- fp16 mma.sync GEMM: C = A * B^T ----------------------------
// CTA 128x128, 4 warps (2x2), warp tile 64x64. K = 4096, KC = 64.
// mode 0: plain fp32 store, 2-term (A = Ah+Al).
// mode 1: fused RoPE/scale/split QKV epilogue, 2-term.
// mode 2: plain fp32 store, 1-term (A = Ah only; Al ignored).
#define GK       4096
#define NCHUNK   (GK / 64)
#define PTILEB   (128 * 128)
#define STAGEB   (3 * PTILEB)
#define GEMM_SMEM (2 * STAGEB)

__global__ __launch_bounds__(128, 2) void gemm_mma(
    const __half* __restrict__ Ah, const __half* __restrict__ Al,
    const __half* __restrict__ Bh, float* __restrict__ C, int N, int mode,
    const float* __restrict__ cosf_, const float* __restrict__ sinf_,
    float* __restrict__ kcache, float* __restrict__ vcache,
    __nv_bfloat16* __restrict__ qhi, __nv_bfloat16* __restrict__ qlo,
    __nv_bfloat16* __restrict__ khi, __nv_bfloat16* __restrict__ klo,
    __half* __restrict__ vh)
{
    extern __shared__ __align__(128) char smraw[];
    const uint32_t sb = (uint32_t)__cvta_generic_to_shared(smraw);

    const int tid = threadIdx.x;
    const int w   = tid >> 5;
    const int l   = tid & 31;
    const int wm  = w & 1;
    const int wn  = w >> 1;
    const bool two = (mode != 2);

    const size_t arow_g = (size_t)blockIdx.y * 128 * GK;
    const size_t brow_g = (size_t)blockIdx.x * 128 * GK;
    const char* gp[3] = { (const char*)(Ah + arow_g), (const char*)(Al + arow_g),
                          (const char*)(Bh + brow_g) };

    auto load_chunk = [&](int t, uint32_t st) {
        const size_t gk = (size_t)t * 128;
#pragma unroll
        for (int part = 0; part < 3; part++) {
            if (part == 1 && !two) continue;
#pragma unroll
            for (int j = 0; j < 8; j++) {
                int slot = tid + j * 128;
                int r = slot >> 3, c = slot & 7;
                uint32_t dc = (uint32_t)((c ^ (r & 7)) * 16);
                cp16(st + part * PTILEB + r * 128 + dc,
                     gp[part] + (size_t)r * (GK * 2) + gk + c * 16);
            }
        }
    };

    const int arow = wm * 64 + (l & 15);
    const uint32_t arb  = (uint32_t)(arow * 128);
    const int axor = arow & 7;
    const int ac0 = (l >> 4);
    const int l2 = l & 7, sel = l >> 3;
    const int brow = wn * 64 + (sel >> 1) * 8 + l2;
    const uint32_t brb  = (uint32_t)(brow * 128);
    const int bxor = brow & 7;
    const int bc0 = (sel & 1);

    float acc[4][8][4];
#pragma unroll
    for (int mt = 0; mt < 4; mt++)
#pragma unroll
        for (int nt = 0; nt < 8; nt++)
#pragma unroll
            for (int i = 0; i < 4; i++) acc[mt][nt][i] = 0.f;

    load_chunk(0, sb);
    asm volatile("cp.async.commit_group;" ::: "memory");

    for (int k = 0; k < NCHUNK; k++) {
        asm volatile("cp.async.wait_group 0;" ::: "memory");
        __syncthreads();
        if (k + 1 < NCHUNK) {
            load_chunk(k + 1, sb + ((k + 1) & 1) * STAGEB);
            asm volatile("cp.async.commit_group;" ::: "memory");
        }

        const uint32_t st = sb + (k & 1) * STAGEB;
#pragma unroll
        for (int ks = 0; ks < 4; ks++) {
            const uint32_t ach = (uint32_t)(((ks * 2 + ac0) ^ axor) * 16);
            const uint32_t bch = (uint32_t)(((ks * 2 + bc0) ^ bxor) * 16);

            uint32_t ah[4][4], bh[8][2];
#pragma unroll
            for (int mt = 0; mt < 4; mt++)
                ldm4(ah[mt][0], ah[mt][1], ah[mt][2], ah[mt][3],
                     st + arb + mt * 2048 + ach);
#pragma unroll
            for (int np = 0; np < 4; np++)
                ldm4(bh[2*np][0], bh[2*np][1], bh[2*np+1][0], bh[2*np+1][1],
                     st + 2 * PTILEB + brb + np * 2048 + bch);
#pragma unroll
            for (int mt = 0; mt < 4; mt++)
#pragma unroll
                for (int nt = 0; nt < 8; nt++)
                    mma_f16(acc[mt][nt], ah[mt], bh[nt]);

            if (two) {
                uint32_t al[4][4];
#pragma unroll
                for (int mt = 0; mt < 4; mt++)
                    ldm4(al[mt][0], al[mt][1], al[mt][2], al[mt][3],
                         st + PTILEB + arb + mt * 2048 + ach);
#pragma unroll
                for (int mt = 0; mt < 4; mt++)
#pragma unroll
                    for (int nt = 0; nt < 8; nt++)
                        mma_f16(acc[mt][nt], al[mt], bh[nt]);
            }
        }
    }

    const int crow = blockIdx.y * 128 + wm * 64 + (l >> 2);
    const int ccolbase = wn * 64 + (l & 3) * 2;

    if (mode != 1) {
        const int ccol = blockIdx.x * 128 + ccolbase;
#pragma unroll
        for (int mt = 0; mt < 4; mt++) {
#pragma unroll
            for (int nt = 0; nt < 8; nt++) {
                float* p0 = C + (size_t)(crow + mt * 16)     * N + ccol + nt * 8;
                float* p1 = C + (size_t)(crow + mt * 16 + 8) * N + ccol + nt * 8;
                *(float2*)p0 = make_float2(acc[mt][nt][0], acc[mt][nt][1]);
                *(float2*)p1 = make_float2(acc[mt][nt][2], acc[mt][nt][3]);
            }
        }
        return;
    }

    // ---- mode 1: fused QKV epilogue (one head per CTA column block) --------
    const int bx = blockIdx.x;
#pragma unroll
    for (int mt = 0; mt < 4; mt++) {
#pragma unroll
        for (int j = 0; j < 2; j++) {
            const int s = crow + mt * 16 + j * 8;
#pragma unroll
            for (int nt = 0; nt < 8; nt++) {
                float v0 = acc[mt][nt][j * 2 + 0];
                float v1 = acc[mt][nt][j * 2 + 1];
                const int d = ccolbase + nt * 8;
                if (bx < NH) {
                    const int f = d >> 1;
                    float c  = __ldg(cosf_ + s * 64 + f);
                    float sn = __ldg(sinf_ + s * 64 + f);
                    float o1 = (v0 * c - v1 * sn) * SCALE;
                    float o2 = (v0 * sn + v1 * c) * SCALE;
                    size_t o = ((size_t)bx * SEQLEN + s) * HD + d;
                    __nv_bfloat162 h2, l2v;
                    split2bf(o1, o2, h2, l2v);
                    *(__nv_bfloat162*)(qhi + o) = h2;
                    *(__nv_bfloat162*)(qlo + o) = l2v;
                } else if (bx < NH + NKV) {
                    const int kvh = bx - NH;
                    const int f = d >> 1;
                    float c  = __ldg(cosf_ + s * 64 + f);
                    float sn = __ldg(sinf_ + s * 64 + f);
                    float o1 = v0 * c - v1 * sn;
                    float o2 = v0 * sn + v1 * c;
                    *(float2*)(kcache + (size_t)s * KV_ROW + kvh * HD + d) =
                        make_float2(o1, o2);
                    size_t o = ((size_t)kvh * SEQLEN + s) * HD + d;
                    __nv_bfloat162 h2, l2v;
                    split2bf(o1, o2, h2, l2v);
                    *(__nv_bfloat162*)(khi + o) = h2;
                    *(__nv_bfloat162*)(klo + o) = l2v;
                } else {
                    const int kvh = bx - NH - NKV;
                    *(float2*)(vcache + (size_t)s * KV_ROW + kvh * HD + d) =
                        make_float2(v0, v1);
                    size_t o = ((size_t)kvh * SEQLEN + s) * HD + d;
                    *(__half2*)(vh + o) = __floats2half2_rn(v0, v1);
                }
            }
        }
    }
}

// ---------------- tensor-core causal flash attention (double-buffered) ------
// K: bf16 hi/lo 3-term; V: single fp16, P split fp16 hi/lo (2-term PV).
// Epilogue: single fp16 output (A operand of 1-term Wo GEMM).
#define ASTRIDE 272
#define ATILE   (64 * ASTRIDE)
#define ABUF    (3 * ATILE)
#define ATTN_SMEM (2 * ABUF)

__global__ __launch_bounds__(256, 1) void attn_tc(
    const __nv_bfloat16* __restrict__ Qh, const __nv_bfloat16* __restrict__ Ql,
    const __nv_bfloat16* __restrict__ Kh, const __nv_bfloat16* __restrict__ Kl,
    const __half* __restrict__ Vh, __half* __restrict__ OH)
{
    extern __shared__ __align__(128) char smraw[];
    const uint32_t sb = (uint32_t)__cvta_generic_to_shared(smraw);
    const int tid = threadIdx.x, w = tid >> 5, l = tid & 31;
    const int qt  = (int)gridDim.x - 1 - (int)blockIdx.x;
    const int h   = blockIdx.y;
    const int kvh = h >> 2;

    uint32_t qh_[8][4], ql_[8][4];
    {
        const uint32_t aoff = sb + (uint32_t)((w * 16 + (l & 15)) * ASTRIDE
                                              + (l >> 4) * 16);
        for (int part = 0; part < 2; part++) {
            const __nv_bfloat16* src = part ? Ql : Qh;
            const char* g0 = (const char*)(src + ((size_t)h * SEQLEN + qt * 128) * HD);
            for (int i = tid; i < 2048; i += 256)
                cp16(sb + (uint32_t)((i >> 4) * ASTRIDE + (i & 15) * 16),
                     g0 + (size_t)i * 16);
            asm volatile("cp.async.commit_group;" ::: "memory");
            asm volatile("cp.async.wait_group 0;" ::: "memory");
            __syncthreads();
            uint32_t (*dst)[4] = part ? ql_ : qh_;
#pragma unroll
            for (int g = 0; g < 8; g++)
                ldm4(dst[g][0], dst[g][1], dst[g][2], dst[g][3], aoff + g * 32);
            __syncthreads();
        }
    }

    float o[16][4];
#pragma unroll
    for (int t = 0; t < 16; t++)
#pragma unroll
        for (int i = 0; i < 4; i++) o[t][i] = 0.f;
    float m0 = -1e30f, m1 = -1e30f, l0 = 0.f, l1 = 0.f;

    const int row0 = qt * 128 + w * 16 + (l >> 2);
    const int l2 = l & 7, sel = l >> 3;
    const int nkb = 2 * qt + 2;

    auto load_kv = [&](int kb, uint32_t bufbase) {
        const size_t gbase = (((size_t)kvh * SEQLEN + (size_t)kb * 64) * HD) * 2;
        for (int i = tid; i < 1024; i += 256) {
            uint32_t soff = (uint32_t)((i >> 4) * ASTRIDE + (i & 15) * 16);
            size_t goff = gbase + (size_t)i * 16;
            cp16(bufbase + 0 * ATILE + soff, (const char*)Kh + goff);
            cp16(bufbase + 1 * ATILE + soff, (const char*)Kl + goff);
            cp16(bufbase + 2 * ATILE + soff, (const char*)Vh + goff);
        }
        asm volatile("cp.async.commit_group;" ::: "memory");
    };

    int buf = 0;
    load_kv(0, sb);

    for (int kb = 0; kb < nkb; kb++) {
        if (kb + 1 < nkb) {
            load_kv(kb + 1, sb + (buf ^ 1) * ABUF);
            asm volatile("cp.async.wait_group 1;" ::: "memory");
        } else {
            asm volatile("cp.async.wait_group 0;" ::: "memory");
        }
        __syncthreads();
        const uint32_t bbase = sb + buf * ABUF;

        float sc[8][4];
#pragma unroll
        for (int t = 0; t < 8; t++)
#pragma unroll
            for (int i = 0; i < 4; i++) sc[t][i] = 0.f;

#pragma unroll
        for (int g = 0; g < 8; g++) {
#pragma unroll
            for (int n16 = 0; n16 < 4; n16++) {
                uint32_t kaddr = bbase + (uint32_t)((n16 * 16 + (sel >> 1) * 8 + l2)
                                                    * ASTRIDE + (sel & 1) * 16 + g * 32);
                uint32_t bh[2][2], bl[2][2];
                ldm4(bh[0][0], bh[0][1], bh[1][0], bh[1][1], kaddr);
                ldm4(bl[0][0], bl[0][1], bl[1][0], bl[1][1], kaddr + ATILE);
#pragma unroll
                for (int j = 0; j < 2; j++) {
                    int t = n16 * 2 + j;
                    mma_bf16(sc[t], qh_[g], bh[j]);
                    mma_bf16(sc[t], ql_[g], bh[j]);
                    mma_bf16(sc[t], qh_[g], bl[j]);
                }
            }
        }

        if (kb >= 2 * qt) {
#pragma unroll
            for (int t = 0; t < 8; t++) {
                int col = kb * 64 + t * 8 + 2 * (l & 3);
                if (col     > row0)     sc[t][0] = -1e30f;
                if (col + 1 > row0)     sc[t][1] = -1e30f;
                if (col     > row0 + 8) sc[t][2] = -1e30f;
                if (col + 1 > row0 + 8) sc[t][3] = -1e30f;
            }
        }

        float r0m = -1e30f, r1m = -1e30f;
#pragma unroll
        for (int t = 0; t < 8; t++) {
            r0m = fmaxf(r0m, fmaxf(sc[t][0], sc[t][1]));
            r1m = fmaxf(r1m, fmaxf(sc[t][2], sc[t][3]));
        }
        r0m = fmaxf(r0m, __shfl_xor_sync(0xffffffffu, r0m, 1));
        r0m = fmaxf(r0m, __shfl_xor_sync(0xffffffffu, r0m, 2));
        r1m = fmaxf(r1m, __shfl_xor_sync(0xffffffffu, r1m, 1));
        r1m = fmaxf(r1m, __shfl_xor_sync(0xffffffffu, r1m, 2));
        float nm0 = fmaxf(m0, r0m), nm1 = fmaxf(m1, r1m);
        float a0 = __expf(m0 - nm0), a1 = __expf(m1 - nm1);

        float s0 = 0.f, s1 = 0.f;
#pragma unroll
        for (int t = 0; t < 8; t++) {
            sc[t][0] = __expf(sc[t][0] - nm0); s0 += sc[t][0];
            sc[t][1] = __expf(sc[t][1] - nm0); s0 += sc[t][1];
            sc[t][2] = __expf(sc[t][2] - nm1); s1 += sc[t][2];
            sc[t][3] = __expf(sc[t][3] - nm1); s1 += sc[t][3];
        }
        s0 += __shfl_xor_sync(0xffffffffu, s0, 1);
        s0 += __shfl_xor_sync(0xffffffffu, s0, 2);
        s1 += __shfl_xor_sync(0xffffffffu, s1, 1);
        s1 += __shfl_xor_sync(0xffffffffu, s1, 2);
        l0 = l0 * a0 + s0;
        l1 = l1 * a1 + s1;
        m0 = nm0; m1 = nm1;
#pragma unroll
        for (int t = 0; t < 16; t++) {
            o[t][0] *= a0; o[t][1] *= a0;
            o[t][2] *= a1; o[t][3] *= a1;
        }

        // ---- O += P V : P fp16 hi/lo 2-term, V single fp16 ------------------
#pragma unroll
        for (int g = 0; g < 4; g++) {
            uint32_t aph[4], apl[4];
            split2h(sc[2*g][0],   sc[2*g][1],   aph[0], apl[0]);
            split2h(sc[2*g][2],   sc[2*g][3],   aph[1], apl[1]);
            split2h(sc[2*g+1][0], sc[2*g+1][1], aph[2], apl[2]);
            split2h(sc[2*g+1][2], sc[2*g+1][3], aph[3], apl[3]);
#pragma unroll
            for (int n16 = 0; n16 < 8; n16++) {
                uint32_t vaddr = bbase + 2 * ATILE
                    + (uint32_t)((g * 16 + (l & 15)) * ASTRIDE
                                 + n16 * 32 + (l >> 4) * 16);
                uint32_t bvh[2][2];
                ldm4t(bvh[0][0], bvh[0][1], bvh[1][0], bvh[1][1], vaddr);
#pragma unroll
                for (int j = 0; j < 2; j++) {
                    int t = n16 * 2 + j;
                    mma_f16(o[t], aph, bvh[j]);
                    mma_f16(o[t], apl, bvh[j]);
                }
            }
        }
        __syncthreads();
        buf ^= 1;
    }

    // ---- epilogue: single fp16 output ---------------------------------------
    float i0 = 1.f / l0, i1 = 1.f / l1;
    const int colb = h * HD + 2 * (l & 3);
#pragma unroll
    for (int t = 0; t < 16; t++) {
        *(__half2*)(OH + (size_t)row0 * DIM + colb + t * 8) =
            __floats2half2_rn(o[t][0] * i0, o[t][1] * i0);
        *(__half2*)(OH + (size_t)(row0 + 8) * DIM + colb + t * 8) =
            __floats2half2_rn(o[t][2] * i1, o[t][3] * i1);
    }
}

// ---------------- launch ----------------------------------------------------
extern "C" void kernel_launch(void* const* d_in, const int* in_sizes, int n_in,
                              void* d_out, int out_size)
{
    const float* x     = (const float*)d_in[0];
    const float* cosf_ = (const float*)d_in[1];
    const float* sinf_ = (const float*)d_in[2];
    const float* in_ck = (const float*)d_in[5];
    const float* in_cv = (const float*)d_in[6];
    const float* Wqkv  = (const float*)d_in[7];
    const float* Wo    = (const float*)d_in[8];

    float* out     = (float*)d_out;
    float* cache_k = out + (size_t)SEQLEN * DIM;
    float* cache_v = cache_k + (size_t)WIN * KV_ROW;

    __half *xh_p, *xl_p, *ah_p, *wq_p, *wo_p, *vh_p;
    __nv_bfloat16 *qhi_p, *qlo_p, *khi_p, *klo_p;
    cudaGetSymbolAddress((void**)&xh_p,   g_xh);
    cudaGetSymbolAddress((void**)&xl_p,   g_xl);
    cudaGetSymbolAddress((void**)&ah_p,   g_ah);
    cudaGetSymbolAddress((void**)&wq_p,   g_wq);
    cudaGetSymbolAddress((void**)&wo_p,   g_wo);
    cudaGetSymbolAddress((void**)&vh_p,   g_vh);
    cudaGetSymbolAddress((void**)&qhi_p,  g_qhi);
    cudaGetSymbolAddress((void**)&qlo_p,  g_qlo);
    cudaGetSymbolAddress((void**)&khi_p,  g_khi);
    cudaGetSymbolAddress((void**)&klo_p,  g_klo);

    cudaFuncSetAttribute(gemm_mma, cudaFuncAttributeMaxDynamicSharedMemorySize,
                         GEMM_SMEM);
    cudaFuncSetAttribute(attn_tc, cudaFuncAttributeMaxDynamicSharedMemorySize,
                         ATTN_SMEM);

    // 0) one bandwidth-bound prep kernel
    prep_all<<<(unsigned)((PREP_TOTAL + 255) / 256), 256>>>(
        x, xh_p, xl_p, Wqkv, wq_p, Wo, wo_p,
        in_ck, cache_k, in_cv, cache_v);

    // 1) QKV projection w/ fused RoPE/scale/cache/split epilogue (mode 1)
    gemm_mma<<<dim3(QKV_N / 128, SEQLEN / 128), 128, GEMM_SMEM>>>(
        xh_p, xl_p, wq_p, nullptr, QKV_N, 1,
        cosf_, sinf_, cache_k, cache_v,
        qhi_p, qlo_p, khi_p, klo_p, vh_p);

    // 2) tensor-core causal flash attention -> single fp16 output
    attn_tc<<<dim3(SEQLEN / 128, NH), 256, ATTN_SMEM>>>(
        qhi_p, qlo_p, khi_p, klo_p, vh_p, ah_p);

    // 3) output projection (mode 2: 1-term fp16)
    gemm_mma<<<dim3(DIM / 128, SEQLEN / 128), 128, GEMM_SMEM>>>(
        ah_p, nullptr, wo_p, out, DIM, 2,
        nullptr, nullptr, nullptr, nullptr,
        nullptr, nullptr, nullptr, nullptr, nullptr);
}

// round 17
// speedup vs baseline: 1.2888x; 1.0628x over previous
#include <cuda_runtime.h>
#include <cuda_bf16.h>
#include <cuda_fp16.h>
#include <cstdint>
#include <math.h>

#define SEQLEN 2048
#define DIM    4096
#define NH     32
#define HD     128
#define NKV    8
#define QKV_N  6144
#define KV_ROW 1024
#define WIN    4096
#define SCALE  0.08838834764831845f

// ---------------- scratch (device globals) ----------------------------------
__device__ __half g_xh [(size_t)SEQLEN * DIM];
__device__ __half g_xl [(size_t)SEQLEN * DIM];
__device__ __half g_ah [(size_t)SEQLEN * DIM];
__device__ __half g_wq [(size_t)QKV_N * DIM];
__device__ __half g_wo [(size_t)DIM * DIM];
__device__ __half g_qhi[(size_t)NH  * SEQLEN * HD];    // Q fp16 hi
__device__ __half g_qlo[(size_t)NH  * SEQLEN * HD];    // Q fp16 lo
__device__ __half g_kh [(size_t)NKV * SEQLEN * HD];    // K single fp16
__device__ __half g_vh [(size_t)NKV * SEQLEN * HD];    // V single fp16

// ---------------- common PTX helpers ----------------------------------------
__device__ __forceinline__ void cp16(uint32_t d, const void* g) {
    asm volatile("cp.async.cg.shared.global [%0], [%1], 16;\n"
                 :: "r"(d), "l"(__cvta_generic_to_global(g)) : "memory");
}
__device__ __forceinline__ void ldm4(uint32_t& r0, uint32_t& r1,
                                     uint32_t& r2, uint32_t& r3, uint32_t a) {
    asm volatile("ldmatrix.sync.aligned.m8n8.x4.shared.b16 {%0,%1,%2,%3}, [%4];"
                 : "=r"(r0), "=r"(r1), "=r"(r2), "=r"(r3) : "r"(a));
}
__device__ __forceinline__ void ldm4t(uint32_t& r0, uint32_t& r1,
                                      uint32_t& r2, uint32_t& r3, uint32_t a) {
    asm volatile("ldmatrix.sync.aligned.m8n8.x4.trans.shared.b16 {%0,%1,%2,%3}, [%4];"
                 : "=r"(r0), "=r"(r1), "=r"(r2), "=r"(r3) : "r"(a));
}
__device__ __forceinline__ void mma_f16(float* c, const uint32_t* a,
                                        const uint32_t* b) {
    asm volatile(
        "mma.sync.aligned.m16n8k16.row.col.f32.f16.f16.f32 "
        "{%0,%1,%2,%3}, {%4,%5,%6,%7}, {%8,%9}, {%0,%1,%2,%3};"
        : "+f"(c[0]), "+f"(c[1]), "+f"(c[2]), "+f"(c[3])
        : "r"(a[0]), "r"(a[1]), "r"(a[2]), "r"(a[3]), "r"(b[0]), "r"(b[1]));
}
__device__ __forceinline__ void split2h(float x, float y, uint32_t& hi, uint32_t& lo) {
    __half2 h = __floats2half2_rn(x, y);
    float rx = x - __half2float(__low2half(h));
    float ry = y - __half2float(__high2half(h));
    __half2 r = __floats2half2_rn(rx, ry);
    hi = *(uint32_t*)&h; lo = *(uint32_t*)&r;
}

// ---------------- single prep kernel: all converts + cache tail copies ------
#define XQ4  ((long long)SEQLEN * DIM / 4)
#define WQQ4 ((long long)QKV_N * DIM / 4)
#define WOQ4 ((long long)DIM * DIM / 4)
#define CKQ4 ((long long)(WIN - SEQLEN) * KV_ROW / 4)
#define PREP_TOTAL (XQ4 + WQQ4 + WOQ4 + 2 * CKQ4)

__global__ __launch_bounds__(256) void prep_all(
    const float* __restrict__ x, __half* __restrict__ xh, __half* __restrict__ xl,
    const float* __restrict__ wq, __half* __restrict__ wqh,
    const float* __restrict__ wo, __half* __restrict__ woh,
    const float* __restrict__ in_ck, float* __restrict__ kcache,
    const float* __restrict__ in_cv, float* __restrict__ vcache)
{
    long long i = (long long)blockIdx.x * 256 + threadIdx.x;
    if (i < XQ4) {
        float4 v = ((const float4*)x)[i];
        float vv[4] = {v.x, v.y, v.z, v.w};
        union { unsigned long long u; __half h[4]; } H, L;
#pragma unroll
        for (int j = 0; j < 4; j++) {
            __half h = __float2half_rn(vv[j]);
            H.h[j] = h;
            L.h[j] = __float2half_rn(vv[j] - __half2float(h));
        }
        ((unsigned long long*)xh)[i] = H.u;
        ((unsigned long long*)xl)[i] = L.u;
    } else if (i < XQ4 + WQQ4) {
        long long k = i - XQ4;
        float4 v = ((const float4*)wq)[k];
        union { unsigned long long u; __half h[4]; } H;
        H.h[0] = __float2half_rn(v.x); H.h[1] = __float2half_rn(v.y);
        H.h[2] = __float2half_rn(v.z); H.h[3] = __float2half_rn(v.w);
        ((unsigned long long*)wqh)[k] = H.u;
    } else if (i < XQ4 + WQQ4 + WOQ4) {
        long long k = i - XQ4 - WQQ4;
        float4 v = ((const float4*)wo)[k];
        union { unsigned long long u; __half h[4]; } H;
        H.h[0] = __float2half_rn(v.x); H.h[1] = __float2half_rn(v.y);
        H.h[2] = __float2half_rn(v.z); H.h[3] = __float2half_rn(v.w);
        ((unsigned long long*)woh)[k] = H.u;
    } else if (i < XQ4 + WQQ4 + WOQ4 + CKQ4) {
        long long j = i - XQ4 - WQQ4 - WOQ4 + (long long)SEQLEN * KV_ROW / 4;
        ((float4*)kcache)[j] = ((const float4*)in_ck)[j];
    } else if (i < PREP_TOTAL) {
        long long j = i - XQ4 - WQQ4 - WOQ4 - CKQ4 + (long long)SEQLEN * KV_ROW / 4;
        ((float4*)vcache)[j] = ((const float4*)in_cv)[j];
    }
}

// ---------------- fp16 mma.sync GEMM: C = A * B^T ----------------------------
// mode 0: plain fp32 store, 2-term. mode 1: fused QKV epilogue, 2-term.
// mode 2: plain fp32 store, 1-term.
#define GK       4096
#define NCHUNK   (GK / 64)
#define PTILEB   (128 * 128)
#define STAGEB   (3 * PTILEB)
#define GEMM_SMEM (2 * STAGEB)

__global__ __launch_bounds__(128, 2) void gemm_mma(
    const __half* __restrict__ Ah, const __half* __restrict__ Al,
    const __half* __restrict__ Bh, float* __restrict__ C, int N, int mode,
    const float* __restrict__ cosf_, const float* __restrict__ sinf_,
    float* __restrict__ kcache, float* __restrict__ vcache,
    __half* __restrict__ qhi, __half* __restrict__ qlo,
    __half* __restrict__ kh, __half* __restrict__ vh)
{
    extern __shared__ __align__(128) char smraw[];
    const uint32_t sb = (uint32_t)__cvta_generic_to_shared(smraw);

    const int tid = threadIdx.x;
    const int w   = tid >> 5;
    const int l   = tid & 31;
    const int wm  = w & 1;
    const int wn  = w >> 1;
    const bool two = (mode != 2);

    const size_t arow_g = (size_t)blockIdx.y * 128 * GK;
    const size_t brow_g = (size_t)blockIdx.x * 128 * GK;
    const char* gp[3] = { (const char*)(Ah + arow_g), (const char*)(Al + arow_g),
                          (const char*)(Bh + brow_g) };

    auto load_chunk = [&](int t, uint32_t st) {
        const size_t gk = (size_t)t * 128;
#pragma unroll
        for (int part = 0; part < 3; part++) {
            if (part == 1 && !two) continue;
#pragma unroll
            for (int j = 0; j < 8; j++) {
                int slot = tid + j * 128;
                int r = slot >> 3, c = slot & 7;
                uint32_t dc = (uint32_t)((c ^ (r & 7)) * 16);
                cp16(st + part * PTILEB + r * 128 + dc,
                     gp[part] + (size_t)r * (GK * 2) + gk + c * 16);
            }
        }
    };

    const int arow = wm * 64 + (l & 15);
    const uint32_t arb  = (uint32_t)(arow * 128);
    const int axor = arow & 7;
    const int ac0 = (l >> 4);
    const int l2 = l & 7, sel = l >> 3;
    const int brow = wn * 64 + (sel >> 1) * 8 + l2;
    const uint32_t brb  = (uint32_t)(brow * 128);
    const int bxor = brow & 7;
    const int bc0 = (sel & 1);

    float acc[4][8][4];
#pragma unroll
    for (int mt = 0; mt < 4; mt++)
#pragma unroll
        for (int nt = 0; nt < 8; nt++)
#pragma unroll
            for (int i = 0; i < 4; i++) acc[mt][nt][i] = 0.f;

    load_chunk(0, sb);
    asm volatile("cp.async.commit_group;" ::: "memory");

    for (int k = 0; k < NCHUNK; k++) {
        asm volatile("cp.async.wait_group 0;" ::: "memory");
        __syncthreads();
        if (k + 1 < NCHUNK) {
            load_chunk(k + 1, sb + ((k + 1) & 1) * STAGEB);
            asm volatile("cp.async.commit_group;" ::: "memory");
        }

        const uint32_t st = sb + (k & 1) * STAGEB;
#pragma unroll
        for (int ks = 0; ks < 4; ks++) {
            const uint32_t ach = (uint32_t)(((ks * 2 + ac0) ^ axor) * 16);
            const uint32_t bch = (uint32_t)(((ks * 2 + bc0) ^ bxor) * 16);

            uint32_t ah[4][4], bh[8][2];
#pragma unroll
            for (int mt = 0; mt < 4; mt++)
                ldm4(ah[mt][0], ah[mt][1], ah[mt][2], ah[mt][3],
                     st + arb + mt * 2048 + ach);
#pragma unroll
            for (int np = 0; np < 4; np++)
                ldm4(bh[2*np][0], bh[2*np][1], bh[2*np+1][0], bh[2*np+1][1],
                     st + 2 * PTILEB + brb + np * 2048 + bch);
#pragma unroll
            for (int mt = 0; mt < 4; mt++)
#pragma unroll
                for (int nt = 0; nt < 8; nt++)
                    mma_f16(acc[mt][nt], ah[mt], bh[nt]);

            if (two) {
                uint32_t al[4][4];
#pragma unroll
                for (int mt = 0; mt < 4; mt++)
                    ldm4(al[mt][0], al[mt][1], al[mt][2], al[mt][3],
                         st + PTILEB + arb + mt * 2048 + ach);
#pragma unroll
                for (int mt = 0; mt < 4; mt++)
#pragma unroll
                    for (int nt = 0; nt < 8; nt++)
                        mma_f16(acc[mt][nt], al[mt], bh[nt]);
            }
        }
    }

    const int crow = blockIdx.y * 128 + wm * 64 + (l >> 2);
    const int ccolbase = wn * 64 + (l & 3) * 2;

    if (mode != 1) {
        const int ccol = blockIdx.x * 128 + ccolbase;
#pragma unroll
        for (int mt = 0; mt < 4; mt++) {
#pragma unroll
            for (int nt = 0; nt < 8; nt++) {
                float* p0 = C + (size_t)(crow + mt * 16)     * N + ccol + nt * 8;
                float* p1 = C + (size_t)(crow + mt * 16 + 8) * N + ccol + nt * 8;
                *(float2*)p0 = make_float2(acc[mt][nt][0], acc[mt][nt][1]);
                *(float2*)p1 = make_float2(acc[mt][nt][2], acc[mt][nt][3]);
            }
        }
        return;
    }

    // ---- mode 1: fused QKV epilogue (one head per CTA column block) --------
    const int bx = blockIdx.x;
#pragma unroll
    for (int mt = 0; mt < 4; mt++) {
#pragma unroll
        for (int j = 0; j < 2; j++) {
            const int s = crow + mt * 16 + j * 8;
#pragma unroll
            for (int nt = 0; nt < 8; nt++) {
                float v0 = acc[mt][nt][j * 2 + 0];
                float v1 = acc[mt][nt][j * 2 + 1];
                const int d = ccolbase + nt * 8;
                if (bx < NH) {                      // Q: rope + scale, fp16 hi/lo
                    const int f = d >> 1;
                    float c  = __ldg(cosf_ + s * 64 + f);
                    float sn = __ldg(sinf_ + s * 64 + f);
                    float o1 = (v0 * c - v1 * sn) * SCALE;
                    float o2 = (v0 * sn + v1 * c) * SCALE;
                    size_t o = ((size_t)bx * SEQLEN + s) * HD + d;
                    uint32_t h2, l2v;
                    split2h(o1, o2, h2, l2v);
                    *(uint32_t*)(qhi + o) = h2;
                    *(uint32_t*)(qlo + o) = l2v;
                } else if (bx < NH + NKV) {          // K: rope + cache + fp16
                    const int kvh = bx - NH;
                    const int f = d >> 1;
                    float c  = __ldg(cosf_ + s * 64 + f);
                    float sn = __ldg(sinf_ + s * 64 + f);
                    float o1 = v0 * c - v1 * sn;
                    float o2 = v0 * sn + v1 * c;
                    *(float2*)(kcache + (size_t)s * KV_ROW + kvh * HD + d) =
                        make_float2(o1, o2);
                    size_t o = ((size_t)kvh * SEQLEN + s) * HD + d;
                    *(__half2*)(kh + o) = __floats2half2_rn(o1, o2);
                } else {                             // V: copy + cache + fp16
                    const int kvh = bx - NH - NKV;
                    *(float2*)(vcache + (size_t)s * KV_ROW + kvh * HD + d) =
                        make_float2(v0, v1);
                    size_t o = ((size_t)kvh * SEQLEN + s) * HD + d;
                    *(__half2*)(vh + o) = __floats2half2_rn(v0, v1);
                }
            }
        }
    }
}

// ---------------- tensor-core causal flash attention (double-buffered) ------
// QK: fp16 2-term (Q hi/lo, K single). PV: fp16 2-term (P hi/lo, V single).
#define ASTRIDE 272
#define ATILE   (64 * ASTRIDE)
#define ABUF    (2 * ATILE)              // Kh | Vh = 34816
#define ATTN_SMEM (2 * ABUF)             // 69632

__global__ __launch_bounds__(256, 1) void attn_tc(
    const __half* __restrict__ Qh, const __half* __restrict__ Ql,
    const __half* __restrict__ Kh, const __half* __restrict__ Vh,
    __half* __restrict__ OH)
{
    extern __shared__ __align__(128) char smraw[];
    const uint32_t sb = (uint32_t)__cvta_generic_to_shared(smraw);
    const int tid = threadIdx.x, w = tid >> 5, l = tid & 31;
    const int qt  = (int)gridDim.x - 1 - (int)blockIdx.x;
    const int h   = blockIdx.y;
    const int kvh = h >> 2;

    uint32_t qh_[8][4], ql_[8][4];
    {
        const uint32_t aoff = sb + (uint32_t)((w * 16 + (l & 15)) * ASTRIDE
                                              + (l >> 4) * 16);
        for (int part = 0; part < 2; part++) {
            const __half* src = part ? Ql : Qh;
            const char* g0 = (const char*)(src + ((size_t)h * SEQLEN + qt * 128) * HD);
            for (int i = tid; i < 2048; i += 256)
                cp16(sb + (uint32_t)((i >> 4) * ASTRIDE + (i & 15) * 16),
                     g0 + (size_t)i * 16);
            asm volatile("cp.async.commit_group;" ::: "memory");
            asm volatile("cp.async.wait_group 0;" ::: "memory");
            __syncthreads();
            uint32_t (*dst)[4] = part ? ql_ : qh_;
#pragma unroll
            for (int g = 0; g < 8; g++)
                ldm4(dst[g][0], dst[g][1], dst[g][2], dst[g][3], aoff + g * 32);
            __syncthreads();
        }
    }

    float o[16][4];
#pragma unroll
    for (int t = 0; t < 16; t++)
#pragma unroll
        for (int i = 0; i < 4; i++) o[t][i] = 0.f;
    float m0 = -1e30f, m1 = -1e30f, l0 = 0.f, l1 = 0.f;

    const int row0 = qt * 128 + w * 16 + (l >> 2);
    const int l2 = l & 7, sel = l >> 3;
    const int nkb = 2 * qt + 2;

    auto load_kv = [&](int kb, uint32_t bufbase) {
        const size_t gbase = (((size_t)kvh * SEQLEN + (size_t)kb * 64) * HD) * 2;
        for (int i = tid; i < 1024; i += 256) {
            uint32_t soff = (uint32_t)((i >> 4) * ASTRIDE + (i & 15) * 16);
            size_t goff = gbase + (size_t)i * 16;
            cp16(bufbase + 0 * ATILE + soff, (const char*)Kh + goff);
            cp16(bufbase + 1 * ATILE + soff, (const char*)Vh + goff);
        }
        asm volatile("cp.async.commit_group;" ::: "memory");
    };

    int buf = 0;
    load_kv(0, sb);

    for (int kb = 0; kb < nkb; kb++) {
        if (kb + 1 < nkb) {
            load_kv(kb + 1, sb + (buf ^ 1) * ABUF);
            asm volatile("cp.async.wait_group 1;" ::: "memory");
        } else {
            asm volatile("cp.async.wait_group 0;" ::: "memory");
        }
        __syncthreads();
        const uint32_t bbase = sb + buf * ABUF;

        float sc[8][4];
#pragma unroll
        for (int t = 0; t < 8; t++)
#pragma unroll
            for (int i = 0; i < 4; i++) sc[t][i] = 0.f;

#pragma unroll
        for (int g = 0; g < 8; g++) {
#pragma unroll
            for (int n16 = 0; n16 < 4; n16++) {
                uint32_t kaddr = bbase + (uint32_t)((n16 * 16 + (sel >> 1) * 8 + l2)
                                                    * ASTRIDE + (sel & 1) * 16 + g * 32);
                uint32_t bh[2][2];
                ldm4(bh[0][0], bh[0][1], bh[1][0], bh[1][1], kaddr);
#pragma unroll
                for (int j = 0; j < 2; j++) {
                    int t = n16 * 2 + j;
                    mma_f16(sc[t], qh_[g], bh[j]);
                    mma_f16(sc[t], ql_[g], bh[j]);
                }
            }
        }

        if (kb >= 2 * qt) {
#pragma unroll
            for (int t = 0; t < 8; t++) {
                int col = kb * 64 + t * 8 + 2 * (l & 3);
                if (col     > row0)     sc[t][0] = -1e30f;
                if (col + 1 > row0)     sc[t][1] = -1e30f;
                if (col     > row0 + 8) sc[t][2] = -1e30f;
                if (col + 1 > row0 + 8) sc[t][3] = -1e30f;
            }
        }

        float r0m = -1e30f, r1m = -1e30f;
#pragma unroll
        for (int t = 0; t < 8; t++) {
            r0m = fmaxf(r0m, fmaxf(sc[t][0], sc[t][1]));
            r1m = fmaxf(r1m, fmaxf(sc[t][2], sc[t][3]));
        }
        r0m = fmaxf(r0m, __shfl_xor_sync(0xffffffffu, r0m, 1));
        r0m = fmaxf(r0m, __shfl_xor_sync(0xffffffffu, r0m, 2));
        r1m = fmaxf(r1m, __shfl_xor_sync(0xffffffffu, r1m, 1));
        r1m = fmaxf(r1m, __shfl_xor_sync(0xffffffffu, r1m, 2));
        float nm0 = fmaxf(m0, r0m), nm1 = fmaxf(m1, r1m);
        float a0 = __expf(m0 - nm0), a1 = __expf(m1 - nm1);

        float s0 = 0.f, s1 = 0.f;
#pragma unroll
        for (int t = 0; t < 8; t++) {
            sc[t][0] = __expf(sc[t][0] - nm0); s0 += sc[t][0];
            sc[t][1] = __expf(sc[t][1] - nm0); s0 += sc[t][1];
            sc[t][2] = __expf(sc[t][2] - nm1); s1 += sc[t][2];
            sc[t][3] = __expf(sc[t][3] - nm1); s1 += sc[t][3];
        }
        s0 += __shfl_xor_sync(0xffffffffu, s0, 1);
        s0 += __shfl_xor_sync(0xffffffffu, s0, 2);
        s1 += __shfl_xor_sync(0xffffffffu, s1, 1);
        s1 += __shfl_xor_sync(0xffffffffu, s1, 2);
        l0 = l0 * a0 + s0;
        l1 = l1 * a1 + s1;
        m0 = nm0; m1 = nm1;
#pragma unroll
        for (int t = 0; t < 16; t++) {
            o[t][0] *= a0; o[t][1] *= a0;
            o[t][2] *= a1; o[t][3] *= a1;
        }

        // ---- O += P V : P fp16 hi/lo 2-term, V single fp16 ------------------
#pragma unroll
        for (int g = 0; g < 4; g++) {
            uint32_t aph[4], apl[4];
            split2h(sc[2*g][0],   sc[2*g][1],   aph[0], apl[0]);
            split2h(sc[2*g][2],   sc[2*g][3],   aph[1], apl[1]);
            split2h(sc[2*g+1][0], sc[2*g+1][1], aph[2], apl[2]);
            split2h(sc[2*g+1][2], sc[2*g+1][3], aph[3], apl[3]);
#pragma unroll
            for (int n16 = 0; n16 < 8; n16++) {
                uint32_t vaddr = bbase + 1 * ATILE
                    + (uint32_t)((g * 16 + (l & 15)) * ASTRIDE
                                 + n16 * 32 + (l >> 4) * 16);
                uint32_t bvh[2][2];
                ldm4t(bvh[0][0], bvh[0][1], bvh[1][0], bvh[1][1], vaddr);
#pragma unroll
                for (int j = 0; j < 2; j++) {
                    int t = n16 * 2 + j;
                    mma_f16(o[t], aph, bvh[j]);
                    mma_f16(o[t], apl, bvh[j]);
                }
            }
        }
        __syncthreads();
        buf ^= 1;
    }

    float i0 = 1.f / l0, i1 = 1.f / l1;
    const int colb = h * HD + 2 * (l & 3);
#pragma unroll
    for (int t = 0; t < 16; t++) {
        *(__half2*)(OH + (size_t)row0 * DIM + colb + t * 8) =
            __floats2half2_rn(o[t][0] * i0, o[t][1] * i0);
        *(__half2*)(OH + (size_t)(row0 + 8) * DIM + colb + t * 8) =
            __floats2half2_rn(o[t][2] * i1, o[t][3] * i1);
    }
}

// ---------------- launch ----------------------------------------------------
extern "C" void kernel_launch(void* const* d_in, const int* in_sizes, int n_in,
                              void* d_out, int out_size)
{
    const float* x     = (const float*)d_in[0];
    const float* cosf_ = (const float*)d_in[1];
    const float* sinf_ = (const float*)d_in[2];
    const float* in_ck = (const float*)d_in[5];
    const float* in_cv = (const float*)d_in[6];
    const float* Wqkv  = (const float*)d_in[7];
    const float* Wo    = (const float*)d_in[8];

    float* out     = (float*)d_out;
    float* cache_k = out + (size_t)SEQLEN * DIM;
    float* cache_v = cache_k + (size_t)WIN * KV_ROW;

    __half *xh_p, *xl_p, *ah_p, *wq_p, *wo_p, *qhi_p, *qlo_p, *kh_p, *vh_p;
    cudaGetSymbolAddress((void**)&xh_p,  g_xh);
    cudaGetSymbolAddress((void**)&xl_p,  g_xl);
    cudaGetSymbolAddress((void**)&ah_p,  g_ah);
    cudaGetSymbolAddress((void**)&wq_p,  g_wq);
    cudaGetSymbolAddress((void**)&wo_p,  g_wo);
    cudaGetSymbolAddress((void**)&qhi_p, g_qhi);
    cudaGetSymbolAddress((void**)&qlo_p, g_qlo);
    cudaGetSymbolAddress((void**)&kh_p,  g_kh);
    cudaGetSymbolAddress((void**)&vh_p,  g_vh);

    cudaFuncSetAttribute(gemm_mma, cudaFuncAttributeMaxDynamicSharedMemorySize,
                         GEMM_SMEM);
    cudaFuncSetAttribute(attn_tc, cudaFuncAttributeMaxDynamicSharedMemorySize,
                         ATTN_SMEM);

    // 0) one bandwidth-bound prep kernel
    prep_all<<<(unsigned)((PREP_TOTAL + 255) / 256), 256>>>(
        x, xh_p, xl_p, Wqkv, wq_p, Wo, wo_p,
        in_ck, cache_k, in_cv, cache_v);

    // 1) QKV projection w/ fused RoPE/scale/cache/split epilogue (mode 1)
    gemm_mma<<<dim3(QKV_N / 128, SEQLEN / 128), 128, GEMM_SMEM>>>(
        xh_p, xl_p, wq_p, nullptr, QKV_N, 1,
        cosf_, sinf_, cache_k, cache_v,
        qhi_p, qlo_p, kh_p, vh_p);

    // 2) tensor-core causal flash attention (QK & PV both fp16 2-term)
    attn_tc<<<dim3(SEQLEN / 128, NH), 256, ATTN_SMEM>>>(
        qhi_p, qlo_p, kh_p, vh_p, ah_p);

    // 3) output projection (mode 2: 1-term fp16)
    gemm_mma<<<dim3(DIM / 128, SEQLEN / 128), 128, GEMM_SMEM>>>(
        ah_p, nullptr, wo_p, out, DIM, 2,
        nullptr, nullptr, nullptr, nullptr,
        nullptr, nullptr, nullptr, nullptr);
}